// round 4
// baseline (speedup 1.0000x reference)
#include <cuda_runtime.h>
#include <cuda_bf16.h>

#define B_  4
#define T_  4096
#define C_  64
#define HS_ 64
#define BM  128      // query rows per tile
#define BN  16       // key tile (SMEM) size
#define NT  (T_ / BM)   // 32 q-tiles per batch
#define KC  512      // keys per split-K chunk
#define NCMAX 8      // max chunks per q-tile (tile 31: 4096/512)

// Scratch (device globals — no cudaMalloc allowed).
__device__ float g_q[B_ * T_ * HS_];
__device__ float g_k[B_ * T_ * HS_];
__device__ float g_v[B_ * T_ * HS_];
// Split-K partials: per (b, row, chunk): m, l, o[64]
__device__ float g_pm[B_ * T_ * NCMAX];
__device__ float g_pl[B_ * T_ * NCMAX];
__device__ float g_po[(size_t)B_ * T_ * NCMAX * HS_];

// ---------------------------------------------------------------------------
// Kernel 1: fused QKV projection.
// ---------------------------------------------------------------------------
__global__ __launch_bounds__(128) void qkv_proj_kernel(
    const float* __restrict__ x,
    const float* __restrict__ Wq,
    const float* __restrict__ Wk,
    const float* __restrict__ Wv)
{
    __shared__ float sWq[C_ * HS_];
    __shared__ float sWk[C_ * HS_];
    __shared__ float sWv[C_ * HS_];

    const int tid = threadIdx.x;
    for (int i = tid; i < C_ * HS_; i += 128) {
        sWq[i] = Wq[i];
        sWk[i] = Wk[i];
        sWv[i] = Wv[i];
    }
    __syncthreads();

    const int row = blockIdx.x * 128 + tid;

    float xr[C_];
    const float4* xp = reinterpret_cast<const float4*>(x + (size_t)row * C_);
#pragma unroll
    for (int i = 0; i < C_ / 4; i++) {
        float4 t = xp[i];
        xr[4 * i + 0] = t.x; xr[4 * i + 1] = t.y;
        xr[4 * i + 2] = t.z; xr[4 * i + 3] = t.w;
    }

    float* qo = g_q + (size_t)row * HS_;
    float* ko = g_k + (size_t)row * HS_;
    float* vo = g_v + (size_t)row * HS_;

#pragma unroll 4
    for (int h = 0; h < HS_; h++) {
        float aq = 0.f, ak = 0.f, av = 0.f;
#pragma unroll
        for (int d = 0; d < C_; d++) {
            const float xv = xr[d];
            aq = fmaf(xv, sWq[d * HS_ + h], aq);
            ak = fmaf(xv, sWk[d * HS_ + h], ak);
            av = fmaf(xv, sWv[d * HS_ + h], av);
        }
        qo[h] = aq; ko[h] = ak; vo[h] = av;
    }
}

// ---------------------------------------------------------------------------
// Kernel 2: split-K causal flash attention partials.
// Block = 256 threads: 128 query rows x 2 head-dim halves.
// blockIdx.x in [0,144) maps (heavy-first) to (q-tile t, key-chunk c).
// Each block computes partial (m, l, o) over keys [c*KC, min((c+1)*KC, span)).
// ---------------------------------------------------------------------------
__global__ __launch_bounds__(256, 2) void attn_partial_kernel()
{
    const int b = blockIdx.y;

    // Map flat index -> (t, c), heaviest tiles first.
    int u = blockIdx.x, t = 0, c = 0;
#pragma unroll 1
    for (int tt = NT - 1; tt >= 0; tt--) {
        const int n = tt / 4 + 1;           // ceil((tt+1)*BM / KC)
        if (u < n) { t = tt; c = u; break; }
        u -= n;
    }

    const int q0   = t * BM;
    const int tid  = threadIdx.x;
    const int r    = tid >> 1;              // row within tile
    const int half = tid & 1;               // head-dim half
    const int qi   = q0 + r;
    const int k0c  = c * KC;
    const int kend = min(k0c + KC, (t + 1) * BM);

    __shared__ float sK[BN * HS_];
    __shared__ float sV[BN * HS_];

    // Load this thread's half of the q row.
    float qr[32];
    {
        const float4* qp = reinterpret_cast<const float4*>(
            g_q + ((size_t)b * T_ + qi) * HS_ + half * 32);
#pragma unroll
        for (int i = 0; i < 8; i++) {
            float4 v = qp[i];
            qr[4 * i + 0] = v.x; qr[4 * i + 1] = v.y;
            qr[4 * i + 2] = v.z; qr[4 * i + 3] = v.w;
        }
    }

    float o[32];
#pragma unroll
    for (int i = 0; i < 32; i++) o[i] = 0.f;
    float m = -1e30f;
    float l = 0.f;

    for (int k0 = k0c; k0 < kend; k0 += BN) {
        __syncthreads();
        // Stage K/V tile: 256 float4 each, one per thread.
        {
            const float4* gk = reinterpret_cast<const float4*>(
                g_k + ((size_t)b * T_ + k0) * HS_);
            const float4* gv = reinterpret_cast<const float4*>(
                g_v + ((size_t)b * T_ + k0) * HS_);
            reinterpret_cast<float4*>(sK)[tid] = gk[tid];
            reinterpret_cast<float4*>(sV)[tid] = gv[tid];
        }
        __syncthreads();

        // Warp-uniform skip: k0 and warp row-base are both multiples of 16.
        if (k0 <= qi) {
            const int jmax = min(BN, qi - k0 + 1);

            float s[BN];
            float bmax = -1e30f;
#pragma unroll
            for (int j = 0; j < BN; j++) {
                float a0 = 0.f, a1 = 0.f, a2 = 0.f, a3 = 0.f;
                const float4* kr = reinterpret_cast<const float4*>(
                    sK + j * HS_ + half * 32);
#pragma unroll
                for (int d4 = 0; d4 < 8; d4++) {
                    float4 kv = kr[d4];
                    a0 = fmaf(qr[4 * d4 + 0], kv.x, a0);
                    a1 = fmaf(qr[4 * d4 + 1], kv.y, a1);
                    a2 = fmaf(qr[4 * d4 + 2], kv.z, a2);
                    a3 = fmaf(qr[4 * d4 + 3], kv.w, a3);
                }
                float a = (a0 + a1) + (a2 + a3);
                a += __shfl_xor_sync(0xFFFFFFFFu, a, 1);   // combine halves
                s[j] = (j < jmax) ? a * 8.0f : -1e30f;     // * C**0.5, masked
                bmax = fmaxf(bmax, s[j]);
            }

            const float mnew = fmaxf(m, bmax);
            const float corr = __expf(m - mnew);
            l *= corr;
#pragma unroll
            for (int i = 0; i < 32; i++) o[i] *= corr;

#pragma unroll
            for (int j = 0; j < BN; j++) {
                const float p = __expf(s[j] - mnew);       // 0 for masked j
                l += p;
                const float4* vr = reinterpret_cast<const float4*>(
                    sV + j * HS_ + half * 32);
#pragma unroll
                for (int d4 = 0; d4 < 8; d4++) {
                    float4 vv = vr[d4];
                    o[4 * d4 + 0] = fmaf(p, vv.x, o[4 * d4 + 0]);
                    o[4 * d4 + 1] = fmaf(p, vv.y, o[4 * d4 + 1]);
                    o[4 * d4 + 2] = fmaf(p, vv.z, o[4 * d4 + 2]);
                    o[4 * d4 + 3] = fmaf(p, vv.w, o[4 * d4 + 3]);
                }
            }
            m = mnew;
        }
    }

    // Write partials.
    const size_t pidx = ((size_t)b * T_ + qi) * NCMAX + c;
    if (half == 0) {
        g_pm[pidx] = m;
        g_pl[pidx] = l;
    }
    float4* pp = reinterpret_cast<float4*>(g_po + pidx * HS_ + half * 32);
#pragma unroll
    for (int i = 0; i < 8; i++) {
        float4 v;
        v.x = o[4 * i + 0]; v.y = o[4 * i + 1];
        v.z = o[4 * i + 2]; v.w = o[4 * i + 3];
        pp[i] = v;
    }
}

// ---------------------------------------------------------------------------
// Kernel 3: merge split-K partials. One thread per (b, row).
// ---------------------------------------------------------------------------
__global__ __launch_bounds__(128) void attn_reduce_kernel(float* __restrict__ out)
{
    const int gid = blockIdx.x * 128 + threadIdx.x;   // over B_*T_
    const int qi  = gid & (T_ - 1);
    const int t   = qi >> 7;                          // q-tile
    const int nc  = t / 4 + 1;                        // chunks for this tile
    const size_t pbase = (size_t)gid * NCMAX;

    float m = -1e30f;
    for (int cc = 0; cc < nc; cc++) m = fmaxf(m, g_pm[pbase + cc]);

    float l = 0.f;
    float o[HS_];
#pragma unroll
    for (int i = 0; i < HS_; i++) o[i] = 0.f;

    for (int cc = 0; cc < nc; cc++) {
        const float w = __expf(g_pm[pbase + cc] - m);
        l = fmaf(g_pl[pbase + cc], w, l);
        const float4* pp = reinterpret_cast<const float4*>(
            g_po + (pbase + cc) * HS_);
#pragma unroll
        for (int i = 0; i < HS_ / 4; i++) {
            float4 v = pp[i];
            o[4 * i + 0] = fmaf(w, v.x, o[4 * i + 0]);
            o[4 * i + 1] = fmaf(w, v.y, o[4 * i + 1]);
            o[4 * i + 2] = fmaf(w, v.z, o[4 * i + 2]);
            o[4 * i + 3] = fmaf(w, v.w, o[4 * i + 3]);
        }
    }

    const float inv = 1.0f / l;
    float4* op = reinterpret_cast<float4*>(out + (size_t)gid * HS_);
#pragma unroll
    for (int i = 0; i < HS_ / 4; i++) {
        float4 v;
        v.x = o[4 * i + 0] * inv;
        v.y = o[4 * i + 1] * inv;
        v.z = o[4 * i + 2] * inv;
        v.w = o[4 * i + 3] * inv;
        op[i] = v;
    }
}

// ---------------------------------------------------------------------------
extern "C" void kernel_launch(void* const* d_in, const int* in_sizes, int n_in,
                              void* d_out, int out_size)
{
    const float* x  = (const float*)d_in[0];
    const float* Wq = (const float*)d_in[1];
    const float* Wk = (const float*)d_in[2];
    const float* Wv = (const float*)d_in[3];
    float* out = (float*)d_out;

    qkv_proj_kernel<<<(B_ * T_) / 128, 128>>>(x, Wq, Wk, Wv);

    // 144 = sum over 32 tiles of ceil((t+1)*128 / 512) chunks
    dim3 pgrid(144, B_);
    attn_partial_kernel<<<pgrid, 256>>>();

    attn_reduce_kernel<<<(B_ * T_) / 128, 128>>>(out);
}

// round 6
// speedup vs baseline: 3.9213x; 3.9213x over previous
#include <cuda_runtime.h>
#include <cuda_fp16.h>
#include <cstdint>

#define B_ 4
#define T_ 4096
#define HS_ 64
#define BM 128
#define KN 64
#define KC 1024
#define NCMAX 4

// Device scratch (no cudaMalloc allowed). 16B-aligned for vector/cp.async access.
__device__ __align__(16) __half g_qh[B_*T_*HS_], g_ql[B_*T_*HS_];
__device__ __align__(16) __half g_kh[B_*T_*HS_], g_kl[B_*T_*HS_];
__device__ __align__(16) __half g_vh[B_*HS_*T_], g_vl[B_*HS_*T_];   // V^T: [b][h][t]
__device__ float g_pm[B_*T_*NCMAX], g_pl[B_*T_*NCMAX];
__device__ float g_po[(size_t)B_*T_*NCMAX*HS_];

// ---------------- PTX helpers (family-agnostic: sm_80+) ----------------
__device__ __forceinline__ uint32_t smem_u32(const void* p) {
    uint32_t a;
    asm("{ .reg .u64 t; cvta.to.shared.u64 t, %1; cvt.u32.u64 %0, t; }" : "=r"(a) : "l"(p));
    return a;
}
#define CP_ASYNC16(dst, src) \
    asm volatile("cp.async.cg.shared.global [%0], [%1], 16;" :: "r"(dst), "l"(src))
#define CP_COMMIT() asm volatile("cp.async.commit_group;" ::: "memory")
#define CP_WAIT(n)  asm volatile("cp.async.wait_group %0;" :: "n"(n) : "memory")

// D(16x8,f32) += A(16x16,f16) * B(16x8,f16)   row.col
#define MMA16816(D0,D1,D2,D3, A0,A1,A2,A3, B0,B1) \
    asm volatile("mma.sync.aligned.m16n8k16.row.col.f32.f16.f16.f32 " \
        "{%0,%1,%2,%3}, {%4,%5,%6,%7}, {%8,%9}, {%0,%1,%2,%3};" \
        : "+f"(D0), "+f"(D1), "+f"(D2), "+f"(D3) \
        : "r"(A0), "r"(A1), "r"(A2), "r"(A3), "r"(B0), "r"(B1))

// ---------------- Kernel 1: projection -> fp16 hi/lo (Q scaled by 8, V transposed)
__global__ __launch_bounds__(128) void proj_kernel(
    const float* __restrict__ x, const float* __restrict__ Wq,
    const float* __restrict__ Wk, const float* __restrict__ Wv)
{
    __shared__ float sW[64 * 64];
    const int which = blockIdx.y;
    const float* W = which == 0 ? Wq : (which == 1 ? Wk : Wv);
    const int tid = threadIdx.x;
    for (int i = tid; i < 4096; i += 128) sW[i] = W[i];
    __syncthreads();

    const int row = blockIdx.x * 128 + tid;
    float xr[64];
    const float4* xp = reinterpret_cast<const float4*>(x + (size_t)row * 64);
#pragma unroll
    for (int i = 0; i < 16; i++) {
        float4 t = xp[i];
        xr[4*i] = t.x; xr[4*i+1] = t.y; xr[4*i+2] = t.z; xr[4*i+3] = t.w;
    }
    const int b = row >> 12, tt = row & (T_ - 1);
#pragma unroll 4
    for (int h = 0; h < 64; h++) {
        float a = 0.f;
#pragma unroll
        for (int d = 0; d < 64; d++) a = fmaf(xr[d], sW[d * 64 + h], a);
        if (which == 0) a *= 8.0f;                 // fold * C**0.5 into Q (exact pow2)
        __half hb = __float2half_rn(a);
        __half lb = __float2half_rn(a - __half2float(hb));
        if (which == 0) { g_qh[(size_t)row*64+h] = hb; g_ql[(size_t)row*64+h] = lb; }
        else if (which == 1) { g_kh[(size_t)row*64+h] = hb; g_kl[(size_t)row*64+h] = lb; }
        else { size_t vi = ((size_t)b*64 + h)*T_ + tt; g_vh[vi] = hb; g_vl[vi] = lb; }
    }
}

// ---------------- Kernel 2: FA2-style mma.sync flash attention (split-K partials)
// SMEM per buffer (32KB): Kh[64][64], Kl, VTh[64][64], VTl — fp16, XOR-swizzled rows.
// Two buffers, cp.async double-buffered.
#define ABYTES 8192
#define BUFBYTES (4 * ABYTES)
#define SMEM_BYTES (2 * BUFBYTES)

extern __shared__ char dsm[];

__device__ __forceinline__ void copy_tile(int b, int k0, int buf, int tid, uint32_t smb)
{
#pragma unroll
    for (int i = 0; i < 8; i++) {
        const int id = tid + i * 256;           // 0..2047
        const int arr = id >> 9;                // 0..3 (uniform per i-range)
        const int r = (id >> 3) & 63;
        const int ch = id & 7;
        const uint32_t dst = smb + buf * BUFBYTES + arr * ABYTES + r * 128 + ((ch ^ (r & 7)) << 4);
        const __half* src;
        if (arr == 0)      src = g_kh + ((size_t)(b * T_ + k0 + r)) * 64 + ch * 8;
        else if (arr == 1) src = g_kl + ((size_t)(b * T_ + k0 + r)) * 64 + ch * 8;
        else if (arr == 2) src = g_vh + ((size_t)(b * 64 + r)) * T_ + k0 + ch * 8;
        else               src = g_vl + ((size_t)(b * 64 + r)) * T_ + k0 + ch * 8;
        CP_ASYNC16(dst, src);
    }
}

__global__ __launch_bounds__(256, 1) void attn_kernel()
{
    const int b = blockIdx.y;
    // heavy-first (t, c) mapping: q-tile t has t/8+1 chunks; sum = 80
    int u = blockIdx.x, t = 0, c = 0;
#pragma unroll 1
    for (int tt = 31; tt >= 0; tt--) { int n = tt / 8 + 1; if (u < n) { t = tt; c = u; break; } u -= n; }
    const int q0 = t * BM, k0c = c * KC;
    const int kend = min(k0c + KC, (t + 1) * BM);
    const int nT = (kend - k0c) / KN;

    const int tid = threadIdx.x, wid = tid >> 5, lane = tid & 31;
    const int g = lane >> 2, tq = lane & 3;
    const int qi0 = q0 + wid * 16;
    const int rg = qi0 + g, rg8 = rg + 8;
    const uint32_t smb = smem_u32(dsm);

    // ---- Q fragments (persistent, from gmem once) ----
    uint32_t qh[16], ql[16];
    {
        const __half* q0p = g_qh + ((size_t)(b * T_ + rg)) * 64;
        const __half* q8p = g_qh + ((size_t)(b * T_ + rg8)) * 64;
        const __half* l0p = g_ql + ((size_t)(b * T_ + rg)) * 64;
        const __half* l8p = g_ql + ((size_t)(b * T_ + rg8)) * 64;
#pragma unroll
        for (int kc = 0; kc < 4; kc++) {
            const int o = 16 * kc + 2 * tq;
            qh[4*kc+0] = *(const uint32_t*)(q0p + o);
            qh[4*kc+1] = *(const uint32_t*)(q8p + o);
            qh[4*kc+2] = *(const uint32_t*)(q0p + o + 8);
            qh[4*kc+3] = *(const uint32_t*)(q8p + o + 8);
            ql[4*kc+0] = *(const uint32_t*)(l0p + o);
            ql[4*kc+1] = *(const uint32_t*)(l8p + o);
            ql[4*kc+2] = *(const uint32_t*)(l0p + o + 8);
            ql[4*kc+3] = *(const uint32_t*)(l8p + o + 8);
        }
    }

    float O[8][4];
#pragma unroll
    for (int j = 0; j < 8; j++) { O[j][0]=0.f; O[j][1]=0.f; O[j][2]=0.f; O[j][3]=0.f; }
    float m0 = -1e30f, m1 = -1e30f, l0 = 0.f, l1 = 0.f;

    copy_tile(b, k0c, 0, tid, smb);
    CP_COMMIT();

    for (int n = 0; n < nT; n++) {
        const int k0 = k0c + n * KN;
        const int buf = n & 1;
        __syncthreads();                          // prev compute done before overwrite
        if (n + 1 < nT) { copy_tile(b, k0 + KN, (n + 1) & 1, tid, smb); CP_COMMIT(); CP_WAIT(1); }
        else            { CP_WAIT(0); }
        __syncthreads();                          // tile n visible to all

        const uint32_t* sKh = (const uint32_t*)(dsm + buf * BUFBYTES);
        const uint32_t* sKl = (const uint32_t*)(dsm + buf * BUFBYTES + ABYTES);
        const uint32_t* sVh = (const uint32_t*)(dsm + buf * BUFBYTES + 2 * ABYTES);
        const uint32_t* sVl = (const uint32_t*)(dsm + buf * BUFBYTES + 3 * ABYTES);

        // ---- S = Q·K^T (3-term hi/lo) ----
        float SD[8][4];
#pragma unroll
        for (int j = 0; j < 8; j++) {
            float d0 = 0.f, d1 = 0.f, d2 = 0.f, d3 = 0.f;
            const int rbase = (8 * j + g) * 32 + tq;
#pragma unroll
            for (int kc = 0; kc < 4; kc++) {
                const int e0 = ((2 * kc) ^ g) << 2;
                const int e1 = ((2 * kc + 1) ^ g) << 2;
                const uint32_t bh0 = sKh[rbase + e0], bh1 = sKh[rbase + e1];
                const uint32_t bl0 = sKl[rbase + e0], bl1 = sKl[rbase + e1];
                MMA16816(d0,d1,d2,d3, qh[4*kc],qh[4*kc+1],qh[4*kc+2],qh[4*kc+3], bh0,bh1);
                MMA16816(d0,d1,d2,d3, ql[4*kc],ql[4*kc+1],ql[4*kc+2],ql[4*kc+3], bh0,bh1);
                MMA16816(d0,d1,d2,d3, qh[4*kc],qh[4*kc+1],qh[4*kc+2],qh[4*kc+3], bl0,bl1);
            }
            SD[j][0]=d0; SD[j][1]=d1; SD[j][2]=d2; SD[j][3]=d3;
        }

        // ---- causal mask (warp-uniform predicate) ----
        if (k0 + KN - 1 > qi0) {
#pragma unroll
            for (int j = 0; j < 8; j++) {
                const int col = k0 + 8 * j + 2 * tq;
                if (col     > rg)  SD[j][0] = -1e30f;
                if (col + 1 > rg)  SD[j][1] = -1e30f;
                if (col     > rg8) SD[j][2] = -1e30f;
                if (col + 1 > rg8) SD[j][3] = -1e30f;
            }
        }

        // ---- online softmax ----
        float bm0 = -1e30f, bm1 = -1e30f;
#pragma unroll
        for (int j = 0; j < 8; j++) {
            bm0 = fmaxf(bm0, fmaxf(SD[j][0], SD[j][1]));
            bm1 = fmaxf(bm1, fmaxf(SD[j][2], SD[j][3]));
        }
        bm0 = fmaxf(bm0, __shfl_xor_sync(0xFFFFFFFFu, bm0, 1));
        bm0 = fmaxf(bm0, __shfl_xor_sync(0xFFFFFFFFu, bm0, 2));
        bm1 = fmaxf(bm1, __shfl_xor_sync(0xFFFFFFFFu, bm1, 1));
        bm1 = fmaxf(bm1, __shfl_xor_sync(0xFFFFFFFFu, bm1, 2));
        const float mn0 = fmaxf(m0, bm0), mn1 = fmaxf(m1, bm1);
        const float c0 = __expf(m0 - mn0), c1 = __expf(m1 - mn1);

        float s0 = 0.f, s1 = 0.f;
#pragma unroll
        for (int j = 0; j < 8; j++) {
            SD[j][0] = __expf(SD[j][0] - mn0);
            SD[j][1] = __expf(SD[j][1] - mn0);
            SD[j][2] = __expf(SD[j][2] - mn1);
            SD[j][3] = __expf(SD[j][3] - mn1);
            s0 += SD[j][0] + SD[j][1];
            s1 += SD[j][2] + SD[j][3];
        }
        s0 += __shfl_xor_sync(0xFFFFFFFFu, s0, 1);
        s0 += __shfl_xor_sync(0xFFFFFFFFu, s0, 2);
        s1 += __shfl_xor_sync(0xFFFFFFFFu, s1, 1);
        s1 += __shfl_xor_sync(0xFFFFFFFFu, s1, 2);
        l0 = fmaf(l0, c0, s0);
        l1 = fmaf(l1, c1, s1);
        m0 = mn0; m1 = mn1;

#pragma unroll
        for (int j = 0; j < 8; j++) {
            O[j][0] *= c0; O[j][1] *= c0; O[j][2] *= c1; O[j][3] *= c1;
        }

        // ---- O += P·V (3-term hi/lo; P fragments packed from S registers) ----
#pragma unroll
        for (int kc = 0; kc < 4; kc++) {
            __half2 h0 = __floats2half2_rn(SD[2*kc][0],   SD[2*kc][1]);
            __half2 h1 = __floats2half2_rn(SD[2*kc][2],   SD[2*kc][3]);
            __half2 h2 = __floats2half2_rn(SD[2*kc+1][0], SD[2*kc+1][1]);
            __half2 h3 = __floats2half2_rn(SD[2*kc+1][2], SD[2*kc+1][3]);
            float2 f0 = __half22float2(h0), f1 = __half22float2(h1);
            float2 f2 = __half22float2(h2), f3 = __half22float2(h3);
            __half2 e0h = __floats2half2_rn(SD[2*kc][0]-f0.x,   SD[2*kc][1]-f0.y);
            __half2 e1h = __floats2half2_rn(SD[2*kc][2]-f1.x,   SD[2*kc][3]-f1.y);
            __half2 e2h = __floats2half2_rn(SD[2*kc+1][0]-f2.x, SD[2*kc+1][1]-f2.y);
            __half2 e3h = __floats2half2_rn(SD[2*kc+1][2]-f3.x, SD[2*kc+1][3]-f3.y);
            const uint32_t pa0 = *(uint32_t*)&h0,  pa1 = *(uint32_t*)&h1;
            const uint32_t pa2 = *(uint32_t*)&h2,  pa3 = *(uint32_t*)&h3;
            const uint32_t pe0 = *(uint32_t*)&e0h, pe1 = *(uint32_t*)&e1h;
            const uint32_t pe2 = *(uint32_t*)&e2h, pe3 = *(uint32_t*)&e3h;
            const int ee0 = ((2 * kc) ^ g) << 2;
            const int ee1 = ((2 * kc + 1) ^ g) << 2;
#pragma unroll
            for (int j = 0; j < 8; j++) {
                const int rbase = (8 * j + g) * 32 + tq;
                const uint32_t vh0 = sVh[rbase + ee0], vh1 = sVh[rbase + ee1];
                const uint32_t vl0 = sVl[rbase + ee0], vl1 = sVl[rbase + ee1];
                MMA16816(O[j][0],O[j][1],O[j][2],O[j][3], pa0,pa1,pa2,pa3, vh0,vh1);
                MMA16816(O[j][0],O[j][1],O[j][2],O[j][3], pe0,pe1,pe2,pe3, vh0,vh1);
                MMA16816(O[j][0],O[j][1],O[j][2],O[j][3], pa0,pa1,pa2,pa3, vl0,vl1);
            }
        }
    }

    // ---- write partials ----
    const size_t p0 = ((size_t)(b * T_ + rg)) * NCMAX + c;
    const size_t p1 = ((size_t)(b * T_ + rg8)) * NCMAX + c;
    if (tq == 0) {
        g_pm[p0] = m0; g_pl[p0] = l0;
        g_pm[p1] = m1; g_pl[p1] = l1;
    }
#pragma unroll
    for (int j = 0; j < 8; j++) {
        float2 a; a.x = O[j][0]; a.y = O[j][1];
        float2 d; d.x = O[j][2]; d.y = O[j][3];
        *(float2*)&g_po[p0 * 64 + 8 * j + 2 * tq] = a;
        *(float2*)&g_po[p1 * 64 + 8 * j + 2 * tq] = d;
    }
}

// ---------------- Kernel 3: merge split-K partials
__global__ __launch_bounds__(128) void attn_reduce_kernel(float* __restrict__ out)
{
    const int gid = blockIdx.x * 128 + threadIdx.x;
    const int qi = gid & (T_ - 1);
    const int nc = (qi >> 7) / 8 + 1;
    const size_t pbase = (size_t)gid * NCMAX;

    float m = -1e30f;
    for (int cc = 0; cc < nc; cc++) m = fmaxf(m, g_pm[pbase + cc]);
    float l = 0.f;
    float o[HS_];
#pragma unroll
    for (int i = 0; i < HS_; i++) o[i] = 0.f;
    for (int cc = 0; cc < nc; cc++) {
        const float w = __expf(g_pm[pbase + cc] - m);
        l = fmaf(g_pl[pbase + cc], w, l);
        const float4* pp = reinterpret_cast<const float4*>(g_po + (pbase + cc) * HS_);
#pragma unroll
        for (int i = 0; i < 16; i++) {
            float4 v = pp[i];
            o[4*i]   = fmaf(w, v.x, o[4*i]);
            o[4*i+1] = fmaf(w, v.y, o[4*i+1]);
            o[4*i+2] = fmaf(w, v.z, o[4*i+2]);
            o[4*i+3] = fmaf(w, v.w, o[4*i+3]);
        }
    }
    const float inv = 1.0f / l;
    float4* op = reinterpret_cast<float4*>(out + (size_t)gid * HS_);
#pragma unroll
    for (int i = 0; i < 16; i++) {
        float4 v;
        v.x = o[4*i] * inv;   v.y = o[4*i+1] * inv;
        v.z = o[4*i+2] * inv; v.w = o[4*i+3] * inv;
        op[i] = v;
    }
}

// ---------------------------------------------------------------------------
extern "C" void kernel_launch(void* const* d_in, const int* in_sizes, int n_in,
                              void* d_out, int out_size)
{
    const float* x  = (const float*)d_in[0];
    const float* Wq = (const float*)d_in[1];
    const float* Wk = (const float*)d_in[2];
    const float* Wv = (const float*)d_in[3];
    float* out = (float*)d_out;

    // >48KB dynamic smem: set attribute every call (host-side API, capture-safe,
    // runs only at capture time — zero cost in timed replays).
    cudaFuncSetAttribute(attn_kernel, cudaFuncAttributeMaxDynamicSharedMemorySize, SMEM_BYTES);

    dim3 pg((B_ * T_) / 128, 3);
    proj_kernel<<<pg, 128>>>(x, Wq, Wk, Wv);

    dim3 ag(80, B_);
    attn_kernel<<<ag, 256, SMEM_BYTES>>>();

    attn_reduce_kernel<<<(B_ * T_) / 128, 128>>>(out);
}

// round 7
// speedup vs baseline: 5.2644x; 1.3425x over previous
#include <cuda_runtime.h>
#include <cuda_fp16.h>
#include <cstdint>

#define B_ 4
#define T_ 4096
#define HS_ 64
#define BM 128
#define KN 64
#define KC 1024
#define NCMAX 4

// Device scratch (no cudaMalloc allowed). 16B-aligned for vector/cp.async access.
__device__ __align__(16) __half g_qh[B_*T_*HS_], g_ql[B_*T_*HS_];
__device__ __align__(16) __half g_kh[B_*T_*HS_], g_kl[B_*T_*HS_];
__device__ __align__(16) __half g_vh[B_*HS_*T_], g_vl[B_*HS_*T_];   // V^T: [b][h][t]
__device__ float g_pm[B_*T_*NCMAX], g_pl[B_*T_*NCMAX];
__device__ float g_po[(size_t)B_*T_*NCMAX*HS_];

// ---------------- PTX helpers (family-agnostic: sm_80+) ----------------
__device__ __forceinline__ uint32_t smem_u32(const void* p) {
    uint32_t a;
    asm("{ .reg .u64 t; cvta.to.shared.u64 t, %1; cvt.u32.u64 %0, t; }" : "=r"(a) : "l"(p));
    return a;
}
#define CP_ASYNC16(dst, src) \
    asm volatile("cp.async.cg.shared.global [%0], [%1], 16;" :: "r"(dst), "l"(src))
#define CP_COMMIT() asm volatile("cp.async.commit_group;" ::: "memory")
#define CP_WAIT(n)  asm volatile("cp.async.wait_group %0;" :: "n"(n) : "memory")

// D(16x8,f32) += A(16x16,f16) * B(16x8,f16)   row.col
#define MMA16816(D0,D1,D2,D3, A0,A1,A2,A3, B0,B1) \
    asm volatile("mma.sync.aligned.m16n8k16.row.col.f32.f16.f16.f32 " \
        "{%0,%1,%2,%3}, {%4,%5,%6,%7}, {%8,%9}, {%0,%1,%2,%3};" \
        : "+f"(D0), "+f"(D1), "+f"(D2), "+f"(D3) \
        : "r"(A0), "r"(A1), "r"(A2), "r"(A3), "r"(B0), "r"(B1))

// ---------------- Kernel 1: projection -> fp16 hi/lo (Q scaled by 8, V transposed)
// Block: 256 threads = 64 rows x 4 h-parts (h uniform per warp -> LDS broadcast).
// W transposed in SMEM for float4 reads; 12 independent FMA chains -> pipe-bound.
__global__ __launch_bounds__(256) void proj_kernel(
    const float* __restrict__ x, const float* __restrict__ Wq,
    const float* __restrict__ Wk, const float* __restrict__ Wv)
{
    __shared__ float sWt[3][64][64];   // [mat][h][d] = W[d*64+h]
    const int tid = threadIdx.x;
    for (int i = tid; i < 4096; i += 256) {
        const int d = i >> 6, h = i & 63;
        sWt[0][h][d] = Wq[i];
        sWt[1][h][d] = Wk[i];
        sWt[2][h][d] = Wv[i];
    }
    __syncthreads();

    const int row = blockIdx.x * 64 + (tid & 63);
    const int hbase = (tid >> 6) << 4;             // 0,16,32,48

    float xr[64];
    const float4* xp = reinterpret_cast<const float4*>(x + (size_t)row * 64);
#pragma unroll
    for (int i = 0; i < 16; i++) {
        float4 t = xp[i];
        xr[4*i] = t.x; xr[4*i+1] = t.y; xr[4*i+2] = t.z; xr[4*i+3] = t.w;
    }
    const int b = row >> 12, tt = row & (T_ - 1);

#pragma unroll 2
    for (int i = 0; i < 16; i++) {
        const int h = hbase + i;
        const float4* wq4 = reinterpret_cast<const float4*>(sWt[0][h]);
        const float4* wk4 = reinterpret_cast<const float4*>(sWt[1][h]);
        const float4* wv4 = reinterpret_cast<const float4*>(sWt[2][h]);
        float q0=0.f,q1=0.f,q2=0.f,q3=0.f;
        float k0=0.f,k1=0.f,k2=0.f,k3=0.f;
        float v0=0.f,v1=0.f,v2=0.f,v3=0.f;
#pragma unroll
        for (int d4 = 0; d4 < 16; d4++) {
            const float4 a = wq4[d4], c = wk4[d4], e = wv4[d4];
            q0 = fmaf(xr[4*d4],   a.x, q0); q1 = fmaf(xr[4*d4+1], a.y, q1);
            q2 = fmaf(xr[4*d4+2], a.z, q2); q3 = fmaf(xr[4*d4+3], a.w, q3);
            k0 = fmaf(xr[4*d4],   c.x, k0); k1 = fmaf(xr[4*d4+1], c.y, k1);
            k2 = fmaf(xr[4*d4+2], c.z, k2); k3 = fmaf(xr[4*d4+3], c.w, k3);
            v0 = fmaf(xr[4*d4],   e.x, v0); v1 = fmaf(xr[4*d4+1], e.y, v1);
            v2 = fmaf(xr[4*d4+2], e.z, v2); v3 = fmaf(xr[4*d4+3], e.w, v3);
        }
        float q = ((q0+q1)+(q2+q3)) * 8.0f;        // fold * C**0.5 (exact pow2)
        float k = (k0+k1)+(k2+k3);
        float v = (v0+v1)+(v2+v3);

        __half qhb = __float2half_rn(q);
        __half qlb = __float2half_rn(q - __half2float(qhb));
        __half khb = __float2half_rn(k);
        __half klb = __float2half_rn(k - __half2float(khb));
        __half vhb = __float2half_rn(v);
        __half vlb = __float2half_rn(v - __half2float(vhb));

        g_qh[(size_t)row*64 + h] = qhb;  g_ql[(size_t)row*64 + h] = qlb;
        g_kh[(size_t)row*64 + h] = khb;  g_kl[(size_t)row*64 + h] = klb;
        const size_t vi = ((size_t)b*64 + h)*T_ + tt;   // coalesced: h uniform per warp
        g_vh[vi] = vhb;  g_vl[vi] = vlb;
    }
}

// ---------------- Kernel 2: FA2-style mma.sync flash attention (split-K partials)
#define ABYTES 8192
#define BUFBYTES (4 * ABYTES)
#define SMEM_BYTES (2 * BUFBYTES)

extern __shared__ char dsm[];

__device__ __forceinline__ void copy_tile(int b, int k0, int buf, int tid, uint32_t smb)
{
#pragma unroll
    for (int i = 0; i < 8; i++) {
        const int id = tid + i * 256;           // 0..2047
        const int arr = id >> 9;                // 0..3 (uniform per i-range)
        const int r = (id >> 3) & 63;
        const int ch = id & 7;
        const uint32_t dst = smb + buf * BUFBYTES + arr * ABYTES + r * 128 + ((ch ^ (r & 7)) << 4);
        const __half* src;
        if (arr == 0)      src = g_kh + ((size_t)(b * T_ + k0 + r)) * 64 + ch * 8;
        else if (arr == 1) src = g_kl + ((size_t)(b * T_ + k0 + r)) * 64 + ch * 8;
        else if (arr == 2) src = g_vh + ((size_t)(b * 64 + r)) * T_ + k0 + ch * 8;
        else               src = g_vl + ((size_t)(b * 64 + r)) * T_ + k0 + ch * 8;
        CP_ASYNC16(dst, src);
    }
}

__global__ __launch_bounds__(256, 1) void attn_kernel()
{
    const int b = blockIdx.y;
    // heavy-first (t, c) mapping: q-tile t has t/8+1 chunks; sum = 80
    int u = blockIdx.x, t = 0, c = 0;
#pragma unroll 1
    for (int tt = 31; tt >= 0; tt--) { int n = tt / 8 + 1; if (u < n) { t = tt; c = u; break; } u -= n; }
    const int q0 = t * BM, k0c = c * KC;
    const int kend = min(k0c + KC, (t + 1) * BM);
    const int nT = (kend - k0c) / KN;

    const int tid = threadIdx.x, wid = tid >> 5, lane = tid & 31;
    const int g = lane >> 2, tq = lane & 3;
    const int qi0 = q0 + wid * 16;
    const int rg = qi0 + g, rg8 = rg + 8;
    const uint32_t smb = smem_u32(dsm);

    // ---- Q fragments (persistent, from gmem once) ----
    uint32_t qh[16], ql[16];
    {
        const __half* q0p = g_qh + ((size_t)(b * T_ + rg)) * 64;
        const __half* q8p = g_qh + ((size_t)(b * T_ + rg8)) * 64;
        const __half* l0p = g_ql + ((size_t)(b * T_ + rg)) * 64;
        const __half* l8p = g_ql + ((size_t)(b * T_ + rg8)) * 64;
#pragma unroll
        for (int kc = 0; kc < 4; kc++) {
            const int o = 16 * kc + 2 * tq;
            qh[4*kc+0] = *(const uint32_t*)(q0p + o);
            qh[4*kc+1] = *(const uint32_t*)(q8p + o);
            qh[4*kc+2] = *(const uint32_t*)(q0p + o + 8);
            qh[4*kc+3] = *(const uint32_t*)(q8p + o + 8);
            ql[4*kc+0] = *(const uint32_t*)(l0p + o);
            ql[4*kc+1] = *(const uint32_t*)(l8p + o);
            ql[4*kc+2] = *(const uint32_t*)(l0p + o + 8);
            ql[4*kc+3] = *(const uint32_t*)(l8p + o + 8);
        }
    }

    float O[8][4];
#pragma unroll
    for (int j = 0; j < 8; j++) { O[j][0]=0.f; O[j][1]=0.f; O[j][2]=0.f; O[j][3]=0.f; }
    float m0 = -1e30f, m1 = -1e30f, l0 = 0.f, l1 = 0.f;

    copy_tile(b, k0c, 0, tid, smb);
    CP_COMMIT();

    for (int n = 0; n < nT; n++) {
        const int k0 = k0c + n * KN;
        const int buf = n & 1;
        __syncthreads();                          // prev compute done before overwrite
        if (n + 1 < nT) { copy_tile(b, k0 + KN, (n + 1) & 1, tid, smb); CP_COMMIT(); CP_WAIT(1); }
        else            { CP_WAIT(0); }
        __syncthreads();                          // tile n visible to all

        const uint32_t* sKh = (const uint32_t*)(dsm + buf * BUFBYTES);
        const uint32_t* sKl = (const uint32_t*)(dsm + buf * BUFBYTES + ABYTES);
        const uint32_t* sVh = (const uint32_t*)(dsm + buf * BUFBYTES + 2 * ABYTES);
        const uint32_t* sVl = (const uint32_t*)(dsm + buf * BUFBYTES + 3 * ABYTES);

        // ---- S = Q·K^T (3-term hi/lo) ----
        float SD[8][4];
#pragma unroll
        for (int j = 0; j < 8; j++) {
            float d0 = 0.f, d1 = 0.f, d2 = 0.f, d3 = 0.f;
            const int rbase = (8 * j + g) * 32 + tq;
#pragma unroll
            for (int kc = 0; kc < 4; kc++) {
                const int e0 = ((2 * kc) ^ g) << 2;
                const int e1 = ((2 * kc + 1) ^ g) << 2;
                const uint32_t bh0 = sKh[rbase + e0], bh1 = sKh[rbase + e1];
                const uint32_t bl0 = sKl[rbase + e0], bl1 = sKl[rbase + e1];
                MMA16816(d0,d1,d2,d3, qh[4*kc],qh[4*kc+1],qh[4*kc+2],qh[4*kc+3], bh0,bh1);
                MMA16816(d0,d1,d2,d3, ql[4*kc],ql[4*kc+1],ql[4*kc+2],ql[4*kc+3], bh0,bh1);
                MMA16816(d0,d1,d2,d3, qh[4*kc],qh[4*kc+1],qh[4*kc+2],qh[4*kc+3], bl0,bl1);
            }
            SD[j][0]=d0; SD[j][1]=d1; SD[j][2]=d2; SD[j][3]=d3;
        }

        // ---- causal mask (warp-uniform predicate) ----
        if (k0 + KN - 1 > qi0) {
#pragma unroll
            for (int j = 0; j < 8; j++) {
                const int col = k0 + 8 * j + 2 * tq;
                if (col     > rg)  SD[j][0] = -1e30f;
                if (col + 1 > rg)  SD[j][1] = -1e30f;
                if (col     > rg8) SD[j][2] = -1e30f;
                if (col + 1 > rg8) SD[j][3] = -1e30f;
            }
        }

        // ---- online softmax ----
        float bm0 = -1e30f, bm1 = -1e30f;
#pragma unroll
        for (int j = 0; j < 8; j++) {
            bm0 = fmaxf(bm0, fmaxf(SD[j][0], SD[j][1]));
            bm1 = fmaxf(bm1, fmaxf(SD[j][2], SD[j][3]));
        }
        bm0 = fmaxf(bm0, __shfl_xor_sync(0xFFFFFFFFu, bm0, 1));
        bm0 = fmaxf(bm0, __shfl_xor_sync(0xFFFFFFFFu, bm0, 2));
        bm1 = fmaxf(bm1, __shfl_xor_sync(0xFFFFFFFFu, bm1, 1));
        bm1 = fmaxf(bm1, __shfl_xor_sync(0xFFFFFFFFu, bm1, 2));
        const float mn0 = fmaxf(m0, bm0), mn1 = fmaxf(m1, bm1);
        const float c0 = __expf(m0 - mn0), c1 = __expf(m1 - mn1);

        float s0 = 0.f, s1 = 0.f;
#pragma unroll
        for (int j = 0; j < 8; j++) {
            SD[j][0] = __expf(SD[j][0] - mn0);
            SD[j][1] = __expf(SD[j][1] - mn0);
            SD[j][2] = __expf(SD[j][2] - mn1);
            SD[j][3] = __expf(SD[j][3] - mn1);
            s0 += SD[j][0] + SD[j][1];
            s1 += SD[j][2] + SD[j][3];
        }
        s0 += __shfl_xor_sync(0xFFFFFFFFu, s0, 1);
        s0 += __shfl_xor_sync(0xFFFFFFFFu, s0, 2);
        s1 += __shfl_xor_sync(0xFFFFFFFFu, s1, 1);
        s1 += __shfl_xor_sync(0xFFFFFFFFu, s1, 2);
        l0 = fmaf(l0, c0, s0);
        l1 = fmaf(l1, c1, s1);
        m0 = mn0; m1 = mn1;

#pragma unroll
        for (int j = 0; j < 8; j++) {
            O[j][0] *= c0; O[j][1] *= c0; O[j][2] *= c1; O[j][3] *= c1;
        }

        // ---- O += P·V (2-term: ph*vh + ph*vl; pl dropped, err ~2^-12 random-sign) ----
#pragma unroll
        for (int kc = 0; kc < 4; kc++) {
            __half2 h0 = __floats2half2_rn(SD[2*kc][0],   SD[2*kc][1]);
            __half2 h1 = __floats2half2_rn(SD[2*kc][2],   SD[2*kc][3]);
            __half2 h2 = __floats2half2_rn(SD[2*kc+1][0], SD[2*kc+1][1]);
            __half2 h3 = __floats2half2_rn(SD[2*kc+1][2], SD[2*kc+1][3]);
            const uint32_t pa0 = *(uint32_t*)&h0, pa1 = *(uint32_t*)&h1;
            const uint32_t pa2 = *(uint32_t*)&h2, pa3 = *(uint32_t*)&h3;
            const int ee0 = ((2 * kc) ^ g) << 2;
            const int ee1 = ((2 * kc + 1) ^ g) << 2;
#pragma unroll
            for (int j = 0; j < 8; j++) {
                const int rbase = (8 * j + g) * 32 + tq;
                const uint32_t vh0 = sVh[rbase + ee0], vh1 = sVh[rbase + ee1];
                const uint32_t vl0 = sVl[rbase + ee0], vl1 = sVl[rbase + ee1];
                MMA16816(O[j][0],O[j][1],O[j][2],O[j][3], pa0,pa1,pa2,pa3, vh0,vh1);
                MMA16816(O[j][0],O[j][1],O[j][2],O[j][3], pa0,pa1,pa2,pa3, vl0,vl1);
            }
        }
    }

    // ---- write partials ----
    const size_t p0 = ((size_t)(b * T_ + rg)) * NCMAX + c;
    const size_t p1 = ((size_t)(b * T_ + rg8)) * NCMAX + c;
    if (tq == 0) {
        g_pm[p0] = m0; g_pl[p0] = l0;
        g_pm[p1] = m1; g_pl[p1] = l1;
    }
#pragma unroll
    for (int j = 0; j < 8; j++) {
        float2 a; a.x = O[j][0]; a.y = O[j][1];
        float2 d; d.x = O[j][2]; d.y = O[j][3];
        *(float2*)&g_po[p0 * 64 + 8 * j + 2 * tq] = a;
        *(float2*)&g_po[p1 * 64 + 8 * j + 2 * tq] = d;
    }
}

// ---------------- Kernel 3: merge split-K partials
__global__ __launch_bounds__(128) void attn_reduce_kernel(float* __restrict__ out)
{
    const int gid = blockIdx.x * 128 + threadIdx.x;
    const int qi = gid & (T_ - 1);
    const int nc = (qi >> 7) / 8 + 1;
    const size_t pbase = (size_t)gid * NCMAX;

    float m = -1e30f;
    for (int cc = 0; cc < nc; cc++) m = fmaxf(m, g_pm[pbase + cc]);
    float l = 0.f;
    float o[HS_];
#pragma unroll
    for (int i = 0; i < HS_; i++) o[i] = 0.f;
    for (int cc = 0; cc < nc; cc++) {
        const float w = __expf(g_pm[pbase + cc] - m);
        l = fmaf(g_pl[pbase + cc], w, l);
        const float4* pp = reinterpret_cast<const float4*>(g_po + (pbase + cc) * HS_);
#pragma unroll
        for (int i = 0; i < 16; i++) {
            float4 v = pp[i];
            o[4*i]   = fmaf(w, v.x, o[4*i]);
            o[4*i+1] = fmaf(w, v.y, o[4*i+1]);
            o[4*i+2] = fmaf(w, v.z, o[4*i+2]);
            o[4*i+3] = fmaf(w, v.w, o[4*i+3]);
        }
    }
    const float inv = 1.0f / l;
    float4* op = reinterpret_cast<float4*>(out + (size_t)gid * HS_);
#pragma unroll
    for (int i = 0; i < 16; i++) {
        float4 v;
        v.x = o[4*i] * inv;   v.y = o[4*i+1] * inv;
        v.z = o[4*i+2] * inv; v.w = o[4*i+3] * inv;
        op[i] = v;
    }
}

// ---------------------------------------------------------------------------
extern "C" void kernel_launch(void* const* d_in, const int* in_sizes, int n_in,
                              void* d_out, int out_size)
{
    const float* x  = (const float*)d_in[0];
    const float* Wq = (const float*)d_in[1];
    const float* Wk = (const float*)d_in[2];
    const float* Wv = (const float*)d_in[3];
    float* out = (float*)d_out;

    cudaFuncSetAttribute(attn_kernel, cudaFuncAttributeMaxDynamicSharedMemorySize, SMEM_BYTES);

    proj_kernel<<<(B_ * T_) / 64, 256>>>(x, Wq, Wk, Wv);

    dim3 ag(80, B_);
    attn_kernel<<<ag, 256, SMEM_BYTES>>>();

    attn_reduce_kernel<<<(B_ * T_) / 128, 128>>>(out);
}

// round 8
// speedup vs baseline: 6.7196x; 1.2764x over previous
#include <cuda_runtime.h>
#include <cuda_fp16.h>
#include <cstdint>

#define B_ 4
#define T_ 4096
#define HS_ 64
#define BM 128
#define KN 64
#define KC 1024
#define NCMAX 4

// Device scratch (no cudaMalloc allowed). 16B-aligned for vector/cp.async access.
__device__ __align__(16) __half g_qh[B_*T_*HS_], g_ql[B_*T_*HS_];
__device__ __align__(16) __half g_kh[B_*T_*HS_], g_kl[B_*T_*HS_];
__device__ __align__(16) __half g_vh[B_*HS_*T_], g_vl[B_*HS_*T_];   // V^T: [b][h][t]
__device__ float g_pm[B_*T_*NCMAX], g_pl[B_*T_*NCMAX];
__device__ float g_po[(size_t)B_*T_*NCMAX*HS_];

// ---------------- PTX helpers (family-agnostic: sm_80+) ----------------
__device__ __forceinline__ uint32_t smem_u32(const void* p) {
    uint32_t a;
    asm("{ .reg .u64 t; cvta.to.shared.u64 t, %1; cvt.u32.u64 %0, t; }" : "=r"(a) : "l"(p));
    return a;
}
#define CP_ASYNC16(dst, src) \
    asm volatile("cp.async.cg.shared.global [%0], [%1], 16;" :: "r"(dst), "l"(src))
#define CP_COMMIT() asm volatile("cp.async.commit_group;" ::: "memory")
#define CP_WAIT(n)  asm volatile("cp.async.wait_group %0;" :: "n"(n) : "memory")

// D(16x8,f32) += A(16x16,f16) * B(16x8,f16)   row.col
#define MMA16816(D0,D1,D2,D3, A0,A1,A2,A3, B0,B1) \
    asm volatile("mma.sync.aligned.m16n8k16.row.col.f32.f16.f16.f32 " \
        "{%0,%1,%2,%3}, {%4,%5,%6,%7}, {%8,%9}, {%0,%1,%2,%3};" \
        : "+f"(D0), "+f"(D1), "+f"(D2), "+f"(D3) \
        : "r"(A0), "r"(A1), "r"(A2), "r"(A3), "r"(B0), "r"(B1))

__device__ __forceinline__ uint32_t h2u(__half2 h) { return *(uint32_t*)&h; }

// ---------------- Kernel 1: tensor-core QKV projection ----------------
// Block: 256 threads (8 warps), 128 rows. A = x (fp16 hi/lo), B = [Wq;Wk;Wv]^T
// stacked as 192x64 (fp16 hi/lo). 3-term MMA. Epilogue: hi/lo split to scratch.
// SMEM: A_h[128][64], A_l, W_h[192][64], W_l  (swizzled rows, 128B each) = 80KB.
#define PA_H 0
#define PA_L 16384
#define PW_H 32768
#define PW_L 57344
#define PROJ_SMEM 81920

extern __shared__ char psm[];

__global__ __launch_bounds__(256) void proj_kernel(
    const float* __restrict__ x, const float* __restrict__ Wq,
    const float* __restrict__ Wk, const float* __restrict__ Wv)
{
    const int tid = threadIdx.x;
    const int wid = tid >> 5, lane = tid & 31;
    const int g = lane >> 2, tq = lane & 3;
    const int rows_base = blockIdx.x * 128;

    // ---- stage x tile (128x64 fp32 -> fp16 hi/lo, swizzled) ----
    // 1024 tasks: (row, ch) ; each = 8 consecutive d
#pragma unroll
    for (int it = 0; it < 4; it++) {
        const int id = tid + it * 256;
        const int r = id >> 3, ch = id & 7;
        const float4* xp = reinterpret_cast<const float4*>(
            x + ((size_t)(rows_base + r)) * 64 + ch * 8);
        const float4 f0 = xp[0], f1 = xp[1];
        uint4 hi, lo;
        __half2 a, bq;
        a = __floats2half2_rn(f0.x, f0.y); hi.x = h2u(a);
        bq = __floats2half2_rn(f0.x - __half2float(__low2half(a)), f0.y - __half2float(__high2half(a))); lo.x = h2u(bq);
        a = __floats2half2_rn(f0.z, f0.w); hi.y = h2u(a);
        bq = __floats2half2_rn(f0.z - __half2float(__low2half(a)), f0.w - __half2float(__high2half(a))); lo.y = h2u(bq);
        a = __floats2half2_rn(f1.x, f1.y); hi.z = h2u(a);
        bq = __floats2half2_rn(f1.x - __half2float(__low2half(a)), f1.y - __half2float(__high2half(a))); lo.z = h2u(bq);
        a = __floats2half2_rn(f1.z, f1.w); hi.w = h2u(a);
        bq = __floats2half2_rn(f1.z - __half2float(__low2half(a)), f1.w - __half2float(__high2half(a))); lo.w = h2u(bq);
        const uint32_t off = r * 128 + ((ch ^ (r & 7)) << 4);
        *reinterpret_cast<uint4*>(psm + PA_H + off) = hi;
        *reinterpret_cast<uint4*>(psm + PA_L + off) = lo;
    }

    // ---- stage W (3 x 64x64 fp32 [d][h] -> stacked [n=mat*64+h][k=d] fp16 hi/lo) ----
    // 1536 tasks: (n, ch); each = 8 d values (strided gmem loads, L1/L2 resident)
#pragma unroll
    for (int it = 0; it < 6; it++) {
        const int id = tid + it * 256;
        const int n = id >> 3, ch = id & 7;
        const int m = n >> 6, h = n & 63;
        const float* W = m == 0 ? Wq : (m == 1 ? Wk : Wv);
        float f[8];
#pragma unroll
        for (int dd = 0; dd < 8; dd++) f[dd] = W[(ch * 8 + dd) * 64 + h];
        uint4 hi, lo;
        uint32_t* hp = &hi.x;
        uint32_t* lp = &lo.x;
#pragma unroll
        for (int p = 0; p < 4; p++) {
            __half2 a = __floats2half2_rn(f[2*p], f[2*p+1]);
            hp[p] = h2u(a);
            __half2 bq = __floats2half2_rn(f[2*p]   - __half2float(__low2half(a)),
                                           f[2*p+1] - __half2float(__high2half(a)));
            lp[p] = h2u(bq);
        }
        const uint32_t off = n * 128 + ((ch ^ (n & 7)) << 4);
        *reinterpret_cast<uint4*>(psm + PW_H + off) = hi;
        *reinterpret_cast<uint4*>(psm + PW_L + off) = lo;
    }
    __syncthreads();

    // ---- MMA: D[16 rows x 192 cols] per warp (24 n-tiles x 4 kc x 3 terms) ----
    const uint32_t* sAh = (const uint32_t*)(psm + PA_H);
    const uint32_t* sAl = (const uint32_t*)(psm + PA_L);
    const uint32_t* sWh = (const uint32_t*)(psm + PW_H);
    const uint32_t* sWl = (const uint32_t*)(psm + PW_L);

    uint32_t ah[16], al[16];
    {
        const int rb  = (wid * 16 + g) * 32 + tq;
        const int rb8 = rb + 256;
#pragma unroll
        for (int kc = 0; kc < 4; kc++) {
            const int e0 = ((2 * kc) ^ g) << 2;
            const int e1 = ((2 * kc + 1) ^ g) << 2;
            ah[4*kc+0] = sAh[rb + e0];  ah[4*kc+1] = sAh[rb8 + e0];
            ah[4*kc+2] = sAh[rb + e1];  ah[4*kc+3] = sAh[rb8 + e1];
            al[4*kc+0] = sAl[rb + e0];  al[4*kc+1] = sAl[rb8 + e0];
            al[4*kc+2] = sAl[rb + e1];  al[4*kc+3] = sAl[rb8 + e1];
        }
    }

    float D[24][4];
#pragma unroll
    for (int j = 0; j < 24; j++) { D[j][0]=0.f; D[j][1]=0.f; D[j][2]=0.f; D[j][3]=0.f; }

#pragma unroll
    for (int j = 0; j < 24; j++) {
        const int rbase = (8 * j + g) * 32 + tq;
#pragma unroll
        for (int kc = 0; kc < 4; kc++) {
            const int e0 = ((2 * kc) ^ g) << 2;
            const int e1 = ((2 * kc + 1) ^ g) << 2;
            const uint32_t bh0 = sWh[rbase + e0], bh1 = sWh[rbase + e1];
            const uint32_t bl0 = sWl[rbase + e0], bl1 = sWl[rbase + e1];
            MMA16816(D[j][0],D[j][1],D[j][2],D[j][3], ah[4*kc],ah[4*kc+1],ah[4*kc+2],ah[4*kc+3], bh0,bh1);
            MMA16816(D[j][0],D[j][1],D[j][2],D[j][3], al[4*kc],al[4*kc+1],al[4*kc+2],al[4*kc+3], bh0,bh1);
            MMA16816(D[j][0],D[j][1],D[j][2],D[j][3], ah[4*kc],ah[4*kc+1],ah[4*kc+2],ah[4*kc+3], bl0,bl1);
        }
    }

    // ---- epilogue: hi/lo split and store ----
    const int rg  = rows_base + wid * 16 + g;
    const int rg8 = rg + 8;
    const int b = rg >> 12, t0 = rg & (T_ - 1), t8 = t0 + 8;

#pragma unroll
    for (int j = 0; j < 24; j++) {
        const int h = 8 * (j & 7) + 2 * tq;
        float v0 = D[j][0], v1 = D[j][1], v2 = D[j][2], v3 = D[j][3];
        if (j < 8) { v0 *= 8.f; v1 *= 8.f; v2 *= 8.f; v3 *= 8.f; }   // Q * C**0.5
        const __half2 hA = __floats2half2_rn(v0, v1);
        const __half2 hB = __floats2half2_rn(v2, v3);
        const __half2 lA = __floats2half2_rn(v0 - __half2float(__low2half(hA)),
                                             v1 - __half2float(__high2half(hA)));
        const __half2 lB = __floats2half2_rn(v2 - __half2float(__low2half(hB)),
                                             v3 - __half2float(__high2half(hB)));
        if (j < 8) {
            *(uint32_t*)&g_qh[(size_t)rg  * 64 + h] = h2u(hA);
            *(uint32_t*)&g_qh[(size_t)rg8 * 64 + h] = h2u(hB);
            *(uint32_t*)&g_ql[(size_t)rg  * 64 + h] = h2u(lA);
            *(uint32_t*)&g_ql[(size_t)rg8 * 64 + h] = h2u(lB);
        } else if (j < 16) {
            *(uint32_t*)&g_kh[(size_t)rg  * 64 + h] = h2u(hA);
            *(uint32_t*)&g_kh[(size_t)rg8 * 64 + h] = h2u(hB);
            *(uint32_t*)&g_kl[(size_t)rg  * 64 + h] = h2u(lA);
            *(uint32_t*)&g_kl[(size_t)rg8 * 64 + h] = h2u(lB);
        } else {
            const size_t r0 = ((size_t)b * 64 + h) * T_;
            const size_t r1 = ((size_t)b * 64 + h + 1) * T_;
            g_vh[r0 + t0] = __low2half(hA);  g_vh[r1 + t0] = __high2half(hA);
            g_vh[r0 + t8] = __low2half(hB);  g_vh[r1 + t8] = __high2half(hB);
            g_vl[r0 + t0] = __low2half(lA);  g_vl[r1 + t0] = __high2half(lA);
            g_vl[r0 + t8] = __low2half(lB);  g_vl[r1 + t8] = __high2half(lB);
        }
    }
}

// ---------------- Kernel 2: FA2-style mma.sync flash attention (split-K partials)
#define ABYTES 8192
#define BUFBYTES (4 * ABYTES)
#define SMEM_BYTES (2 * BUFBYTES)

extern __shared__ char dsm[];

__device__ __forceinline__ void copy_tile(int b, int k0, int buf, int tid, uint32_t smb)
{
#pragma unroll
    for (int i = 0; i < 8; i++) {
        const int id = tid + i * 256;           // 0..2047
        const int arr = id >> 9;                // 0..3 (uniform per i-range)
        const int r = (id >> 3) & 63;
        const int ch = id & 7;
        const uint32_t dst = smb + buf * BUFBYTES + arr * ABYTES + r * 128 + ((ch ^ (r & 7)) << 4);
        const __half* src;
        if (arr == 0)      src = g_kh + ((size_t)(b * T_ + k0 + r)) * 64 + ch * 8;
        else if (arr == 1) src = g_kl + ((size_t)(b * T_ + k0 + r)) * 64 + ch * 8;
        else if (arr == 2) src = g_vh + ((size_t)(b * 64 + r)) * T_ + k0 + ch * 8;
        else               src = g_vl + ((size_t)(b * 64 + r)) * T_ + k0 + ch * 8;
        CP_ASYNC16(dst, src);
    }
}

__global__ __launch_bounds__(256, 2) void attn_kernel()
{
    const int b = blockIdx.y;
    // heavy-first (t, c) mapping: q-tile t has t/8+1 chunks; sum = 80
    int u = blockIdx.x, t = 0, c = 0;
#pragma unroll 1
    for (int tt = 31; tt >= 0; tt--) { int n = tt / 8 + 1; if (u < n) { t = tt; c = u; break; } u -= n; }
    const int q0 = t * BM, k0c = c * KC;
    const int kend = min(k0c + KC, (t + 1) * BM);
    const int nT = (kend - k0c) / KN;

    const int tid = threadIdx.x, wid = tid >> 5, lane = tid & 31;
    const int g = lane >> 2, tq = lane & 3;
    const int qi0 = q0 + wid * 16;
    const int rg = qi0 + g, rg8 = rg + 8;
    const uint32_t smb = smem_u32(dsm);

    // ---- Q fragments (persistent, from gmem once) ----
    uint32_t qh[16], ql[16];
    {
        const __half* q0p = g_qh + ((size_t)(b * T_ + rg)) * 64;
        const __half* q8p = g_qh + ((size_t)(b * T_ + rg8)) * 64;
        const __half* l0p = g_ql + ((size_t)(b * T_ + rg)) * 64;
        const __half* l8p = g_ql + ((size_t)(b * T_ + rg8)) * 64;
#pragma unroll
        for (int kc = 0; kc < 4; kc++) {
            const int o = 16 * kc + 2 * tq;
            qh[4*kc+0] = *(const uint32_t*)(q0p + o);
            qh[4*kc+1] = *(const uint32_t*)(q8p + o);
            qh[4*kc+2] = *(const uint32_t*)(q0p + o + 8);
            qh[4*kc+3] = *(const uint32_t*)(q8p + o + 8);
            ql[4*kc+0] = *(const uint32_t*)(l0p + o);
            ql[4*kc+1] = *(const uint32_t*)(l8p + o);
            ql[4*kc+2] = *(const uint32_t*)(l0p + o + 8);
            ql[4*kc+3] = *(const uint32_t*)(l8p + o + 8);
        }
    }

    float O[8][4];
#pragma unroll
    for (int j = 0; j < 8; j++) { O[j][0]=0.f; O[j][1]=0.f; O[j][2]=0.f; O[j][3]=0.f; }
    float m0 = -1e30f, m1 = -1e30f, l0 = 0.f, l1 = 0.f;

    copy_tile(b, k0c, 0, tid, smb);
    CP_COMMIT();

    for (int n = 0; n < nT; n++) {
        const int k0 = k0c + n * KN;
        const int buf = n & 1;
        __syncthreads();                          // prev compute done before overwrite
        if (n + 1 < nT) { copy_tile(b, k0 + KN, (n + 1) & 1, tid, smb); CP_COMMIT(); CP_WAIT(1); }
        else            { CP_WAIT(0); }
        __syncthreads();                          // tile n visible to all

        const uint32_t* sKh = (const uint32_t*)(dsm + buf * BUFBYTES);
        const uint32_t* sKl = (const uint32_t*)(dsm + buf * BUFBYTES + ABYTES);
        const uint32_t* sVh = (const uint32_t*)(dsm + buf * BUFBYTES + 2 * ABYTES);
        const uint32_t* sVl = (const uint32_t*)(dsm + buf * BUFBYTES + 3 * ABYTES);

        // ---- S = Q·K^T (3-term hi/lo) ----
        float SD[8][4];
#pragma unroll
        for (int j = 0; j < 8; j++) {
            float d0 = 0.f, d1 = 0.f, d2 = 0.f, d3 = 0.f;
            const int rbase = (8 * j + g) * 32 + tq;
#pragma unroll
            for (int kc = 0; kc < 4; kc++) {
                const int e0 = ((2 * kc) ^ g) << 2;
                const int e1 = ((2 * kc + 1) ^ g) << 2;
                const uint32_t bh0 = sKh[rbase + e0], bh1 = sKh[rbase + e1];
                const uint32_t bl0 = sKl[rbase + e0], bl1 = sKl[rbase + e1];
                MMA16816(d0,d1,d2,d3, qh[4*kc],qh[4*kc+1],qh[4*kc+2],qh[4*kc+3], bh0,bh1);
                MMA16816(d0,d1,d2,d3, ql[4*kc],ql[4*kc+1],ql[4*kc+2],ql[4*kc+3], bh0,bh1);
                MMA16816(d0,d1,d2,d3, qh[4*kc],qh[4*kc+1],qh[4*kc+2],qh[4*kc+3], bl0,bl1);
            }
            SD[j][0]=d0; SD[j][1]=d1; SD[j][2]=d2; SD[j][3]=d3;
        }

        // ---- causal mask (warp-uniform predicate) ----
        if (k0 + KN - 1 > qi0) {
#pragma unroll
            for (int j = 0; j < 8; j++) {
                const int col = k0 + 8 * j + 2 * tq;
                if (col     > rg)  SD[j][0] = -1e30f;
                if (col + 1 > rg)  SD[j][1] = -1e30f;
                if (col     > rg8) SD[j][2] = -1e30f;
                if (col + 1 > rg8) SD[j][3] = -1e30f;
            }
        }

        // ---- online softmax ----
        float bm0 = -1e30f, bm1 = -1e30f;
#pragma unroll
        for (int j = 0; j < 8; j++) {
            bm0 = fmaxf(bm0, fmaxf(SD[j][0], SD[j][1]));
            bm1 = fmaxf(bm1, fmaxf(SD[j][2], SD[j][3]));
        }
        bm0 = fmaxf(bm0, __shfl_xor_sync(0xFFFFFFFFu, bm0, 1));
        bm0 = fmaxf(bm0, __shfl_xor_sync(0xFFFFFFFFu, bm0, 2));
        bm1 = fmaxf(bm1, __shfl_xor_sync(0xFFFFFFFFu, bm1, 1));
        bm1 = fmaxf(bm1, __shfl_xor_sync(0xFFFFFFFFu, bm1, 2));
        const float mn0 = fmaxf(m0, bm0), mn1 = fmaxf(m1, bm1);
        const float c0 = __expf(m0 - mn0), c1 = __expf(m1 - mn1);

        float s0 = 0.f, s1 = 0.f;
#pragma unroll
        for (int j = 0; j < 8; j++) {
            SD[j][0] = __expf(SD[j][0] - mn0);
            SD[j][1] = __expf(SD[j][1] - mn0);
            SD[j][2] = __expf(SD[j][2] - mn1);
            SD[j][3] = __expf(SD[j][3] - mn1);
            s0 += SD[j][0] + SD[j][1];
            s1 += SD[j][2] + SD[j][3];
        }
        s0 += __shfl_xor_sync(0xFFFFFFFFu, s0, 1);
        s0 += __shfl_xor_sync(0xFFFFFFFFu, s0, 2);
        s1 += __shfl_xor_sync(0xFFFFFFFFu, s1, 1);
        s1 += __shfl_xor_sync(0xFFFFFFFFu, s1, 2);
        l0 = fmaf(l0, c0, s0);
        l1 = fmaf(l1, c1, s1);
        m0 = mn0; m1 = mn1;

#pragma unroll
        for (int j = 0; j < 8; j++) {
            O[j][0] *= c0; O[j][1] *= c0; O[j][2] *= c1; O[j][3] *= c1;
        }

        // ---- O += P·V (2-term: ph*vh + ph*vl) ----
#pragma unroll
        for (int kc = 0; kc < 4; kc++) {
            __half2 h0 = __floats2half2_rn(SD[2*kc][0],   SD[2*kc][1]);
            __half2 h1 = __floats2half2_rn(SD[2*kc][2],   SD[2*kc][3]);
            __half2 h2 = __floats2half2_rn(SD[2*kc+1][0], SD[2*kc+1][1]);
            __half2 h3 = __floats2half2_rn(SD[2*kc+1][2], SD[2*kc+1][3]);
            const uint32_t pa0 = h2u(h0), pa1 = h2u(h1);
            const uint32_t pa2 = h2u(h2), pa3 = h2u(h3);
            const int ee0 = ((2 * kc) ^ g) << 2;
            const int ee1 = ((2 * kc + 1) ^ g) << 2;
#pragma unroll
            for (int j = 0; j < 8; j++) {
                const int rbase = (8 * j + g) * 32 + tq;
                const uint32_t vh0 = sVh[rbase + ee0], vh1 = sVh[rbase + ee1];
                const uint32_t vl0 = sVl[rbase + ee0], vl1 = sVl[rbase + ee1];
                MMA16816(O[j][0],O[j][1],O[j][2],O[j][3], pa0,pa1,pa2,pa3, vh0,vh1);
                MMA16816(O[j][0],O[j][1],O[j][2],O[j][3], pa0,pa1,pa2,pa3, vl0,vl1);
            }
        }
    }

    // ---- write partials ----
    const size_t p0 = ((size_t)(b * T_ + rg)) * NCMAX + c;
    const size_t p1 = ((size_t)(b * T_ + rg8)) * NCMAX + c;
    if (tq == 0) {
        g_pm[p0] = m0; g_pl[p0] = l0;
        g_pm[p1] = m1; g_pl[p1] = l1;
    }
#pragma unroll
    for (int j = 0; j < 8; j++) {
        float2 a; a.x = O[j][0]; a.y = O[j][1];
        float2 d; d.x = O[j][2]; d.y = O[j][3];
        *(float2*)&g_po[p0 * 64 + 8 * j + 2 * tq] = a;
        *(float2*)&g_po[p1 * 64 + 8 * j + 2 * tq] = d;
    }
}

// ---------------- Kernel 3: merge split-K partials
__global__ __launch_bounds__(128) void attn_reduce_kernel(float* __restrict__ out)
{
    const int gid = blockIdx.x * 128 + threadIdx.x;
    const int qi = gid & (T_ - 1);
    const int nc = (qi >> 7) / 8 + 1;
    const size_t pbase = (size_t)gid * NCMAX;

    float m = -1e30f;
    for (int cc = 0; cc < nc; cc++) m = fmaxf(m, g_pm[pbase + cc]);
    float l = 0.f;
    float o[HS_];
#pragma unroll
    for (int i = 0; i < HS_; i++) o[i] = 0.f;
    for (int cc = 0; cc < nc; cc++) {
        const float w = __expf(g_pm[pbase + cc] - m);
        l = fmaf(g_pl[pbase + cc], w, l);
        const float4* pp = reinterpret_cast<const float4*>(g_po + (pbase + cc) * HS_);
#pragma unroll
        for (int i = 0; i < 16; i++) {
            float4 v = pp[i];
            o[4*i]   = fmaf(w, v.x, o[4*i]);
            o[4*i+1] = fmaf(w, v.y, o[4*i+1]);
            o[4*i+2] = fmaf(w, v.z, o[4*i+2]);
            o[4*i+3] = fmaf(w, v.w, o[4*i+3]);
        }
    }
    const float inv = 1.0f / l;
    float4* op = reinterpret_cast<float4*>(out + (size_t)gid * HS_);
#pragma unroll
    for (int i = 0; i < 16; i++) {
        float4 v;
        v.x = o[4*i] * inv;   v.y = o[4*i+1] * inv;
        v.z = o[4*i+2] * inv; v.w = o[4*i+3] * inv;
        op[i] = v;
    }
}

// ---------------------------------------------------------------------------
extern "C" void kernel_launch(void* const* d_in, const int* in_sizes, int n_in,
                              void* d_out, int out_size)
{
    const float* x  = (const float*)d_in[0];
    const float* Wq = (const float*)d_in[1];
    const float* Wk = (const float*)d_in[2];
    const float* Wv = (const float*)d_in[3];
    float* out = (float*)d_out;

    cudaFuncSetAttribute(proj_kernel, cudaFuncAttributeMaxDynamicSharedMemorySize, PROJ_SMEM);
    cudaFuncSetAttribute(attn_kernel, cudaFuncAttributeMaxDynamicSharedMemorySize, SMEM_BYTES);

    proj_kernel<<<(B_ * T_) / 128, 256, PROJ_SMEM>>>(x, Wq, Wk, Wv);

    dim3 ag(80, B_);
    attn_kernel<<<ag, 256, SMEM_BYTES>>>();

    attn_reduce_kernel<<<(B_ * T_) / 128, 128>>>(out);
}

// round 9
// speedup vs baseline: 7.1243x; 1.0602x over previous
#include <cuda_runtime.h>
#include <cuda_fp16.h>
#include <cstdint>

#define B_ 4
#define T_ 4096
#define HS_ 64
#define BM 128
#define KN 64
#define KC 1024
#define NCMAX 4

// Device scratch (no cudaMalloc allowed). 16B-aligned for vector/cp.async access.
__device__ __align__(16) __half g_qh[B_*T_*HS_], g_ql[B_*T_*HS_];
__device__ __align__(16) __half g_kh[B_*T_*HS_], g_kl[B_*T_*HS_];
__device__ __align__(16) __half g_vh[B_*HS_*T_], g_vl[B_*HS_*T_];   // V^T: [b][h][t]
__device__ __align__(16) __half g_wh[192*64], g_wl[192*64];         // stacked [Wq;Wk;Wv]^T
__device__ float g_pm[B_*T_*NCMAX], g_pl[B_*T_*NCMAX];
__device__ float g_po[(size_t)B_*T_*NCMAX*HS_];

// ---------------- PTX helpers (family-agnostic: sm_80+) ----------------
__device__ __forceinline__ uint32_t smem_u32(const void* p) {
    uint32_t a;
    asm("{ .reg .u64 t; cvta.to.shared.u64 t, %1; cvt.u32.u64 %0, t; }" : "=r"(a) : "l"(p));
    return a;
}
#define CP_ASYNC16(dst, src) \
    asm volatile("cp.async.cg.shared.global [%0], [%1], 16;" :: "r"(dst), "l"(src))
#define CP_COMMIT() asm volatile("cp.async.commit_group;" ::: "memory")
#define CP_WAIT(n)  asm volatile("cp.async.wait_group %0;" :: "n"(n) : "memory")

// D(16x8,f32) += A(16x16,f16) * B(16x8,f16)   row.col
#define MMA16816(D0,D1,D2,D3, A0,A1,A2,A3, B0,B1) \
    asm volatile("mma.sync.aligned.m16n8k16.row.col.f32.f16.f16.f32 " \
        "{%0,%1,%2,%3}, {%4,%5,%6,%7}, {%8,%9}, {%0,%1,%2,%3};" \
        : "+f"(D0), "+f"(D1), "+f"(D2), "+f"(D3) \
        : "r"(A0), "r"(A1), "r"(A2), "r"(A3), "r"(B0), "r"(B1))

__device__ __forceinline__ uint32_t h2u(__half2 h) { return *(uint32_t*)&h; }

// ---------------- Kernel 0: W -> fp16 hi/lo, stacked [n=mat*64+h][k=d] ----------------
__global__ __launch_bounds__(256) void wconv_kernel(
    const float* __restrict__ Wq, const float* __restrict__ Wk, const float* __restrict__ Wv)
{
    const int id = blockIdx.x * 256 + threadIdx.x;    // 0..1535
    const int n = id >> 3, ch = id & 7;
    const int m = n >> 6, h = n & 63;
    const float* W = m == 0 ? Wq : (m == 1 ? Wk : Wv);
    float f[8];
#pragma unroll
    for (int dd = 0; dd < 8; dd++) f[dd] = W[(ch * 8 + dd) * 64 + h];
    uint4 hi, lo;
    uint32_t* hp = &hi.x;
    uint32_t* lp = &lo.x;
#pragma unroll
    for (int p = 0; p < 4; p++) {
        __half2 a = __floats2half2_rn(f[2*p], f[2*p+1]);
        hp[p] = h2u(a);
        __half2 bq = __floats2half2_rn(f[2*p]   - __half2float(__low2half(a)),
                                       f[2*p+1] - __half2float(__high2half(a)));
        lp[p] = h2u(bq);
    }
    *reinterpret_cast<uint4*>(&g_wh[n * 64 + ch * 8]) = hi;
    *reinterpret_cast<uint4*>(&g_wl[n * 64 + ch * 8]) = lo;
}

// ---------------- Kernel 1: tensor-core QKV projection ----------------
// Block: 256 threads (8 warps), 64 rows. warp = (row-group 0..3, n-half 0..1).
// A = x (fp16 hi/lo, 8KB+8KB), B = stacked W (cp.async, 24KB+24KB). 3-term MMA.
#define XA_H 0
#define XA_L 8192
#define WW_H 16384
#define WW_L 40960
#define PROJ_SMEM 65536

extern __shared__ char psm[];

__global__ __launch_bounds__(256, 2) void proj_kernel(const float* __restrict__ x)
{
    const int tid = threadIdx.x;
    const int wid = tid >> 5, lane = tid & 31;
    const int g = lane >> 2, tq = lane & 3;
    const int rows_base = blockIdx.x * 64;
    const uint32_t smb = smem_u32(psm);

    // ---- W tiles via cp.async (coalesced, L2-resident) ----
#pragma unroll
    for (int it = 0; it < 6; it++) {
        const int id = tid + it * 256;            // 0..1535
        const int n = id >> 3, ch = id & 7;
        const uint32_t off = n * 128 + ((ch ^ (n & 7)) << 4);
        CP_ASYNC16(smb + WW_H + off, g_wh + n * 64 + ch * 8);
        CP_ASYNC16(smb + WW_L + off, g_wl + n * 64 + ch * 8);
    }
    CP_COMMIT();

    // ---- x tile: fp32 -> fp16 hi/lo (through regs) ----
#pragma unroll
    for (int it = 0; it < 2; it++) {
        const int id = tid + it * 256;            // 0..511
        const int r = id >> 3, ch = id & 7;
        const float4* xp = reinterpret_cast<const float4*>(
            x + ((size_t)(rows_base + r)) * 64 + ch * 8);
        const float4 f0 = xp[0], f1 = xp[1];
        uint4 hi, lo;
        __half2 a, bq;
        a = __floats2half2_rn(f0.x, f0.y); hi.x = h2u(a);
        bq = __floats2half2_rn(f0.x - __half2float(__low2half(a)), f0.y - __half2float(__high2half(a))); lo.x = h2u(bq);
        a = __floats2half2_rn(f0.z, f0.w); hi.y = h2u(a);
        bq = __floats2half2_rn(f0.z - __half2float(__low2half(a)), f0.w - __half2float(__high2half(a))); lo.y = h2u(bq);
        a = __floats2half2_rn(f1.x, f1.y); hi.z = h2u(a);
        bq = __floats2half2_rn(f1.x - __half2float(__low2half(a)), f1.y - __half2float(__high2half(a))); lo.z = h2u(bq);
        a = __floats2half2_rn(f1.z, f1.w); hi.w = h2u(a);
        bq = __floats2half2_rn(f1.z - __half2float(__low2half(a)), f1.w - __half2float(__high2half(a))); lo.w = h2u(bq);
        const uint32_t off = r * 128 + ((ch ^ (r & 7)) << 4);
        *reinterpret_cast<uint4*>(psm + XA_H + off) = hi;
        *reinterpret_cast<uint4*>(psm + XA_L + off) = lo;
    }
    CP_WAIT(0);
    __syncthreads();

    const uint32_t* sAh = (const uint32_t*)(psm + XA_H);
    const uint32_t* sAl = (const uint32_t*)(psm + XA_L);
    const uint32_t* sWh = (const uint32_t*)(psm + WW_H);
    const uint32_t* sWl = (const uint32_t*)(psm + WW_L);

    // A-fragments (16 rows) persistent
    uint32_t ah[16], al[16];
    {
        const int rb  = ((wid & 3) * 16 + g) * 32 + tq;
        const int rb8 = rb + 256;
#pragma unroll
        for (int kc = 0; kc < 4; kc++) {
            const int e0 = ((2 * kc) ^ g) << 2;
            const int e1 = ((2 * kc + 1) ^ g) << 2;
            ah[4*kc+0] = sAh[rb + e0];  ah[4*kc+1] = sAh[rb8 + e0];
            ah[4*kc+2] = sAh[rb + e1];  ah[4*kc+3] = sAh[rb8 + e1];
            al[4*kc+0] = sAl[rb + e0];  al[4*kc+1] = sAl[rb8 + e0];
            al[4*kc+2] = sAl[rb + e1];  al[4*kc+3] = sAl[rb8 + e1];
        }
    }

    const int nh = wid >> 2;                      // n-half: 0 or 1
    float D[12][4];
#pragma unroll
    for (int j = 0; j < 12; j++) { D[j][0]=0.f; D[j][1]=0.f; D[j][2]=0.f; D[j][3]=0.f; }

#pragma unroll
    for (int jj = 0; jj < 12; jj++) {
        const int jg = nh * 12 + jj;
        const int rbase = (8 * jg + g) * 32 + tq;
#pragma unroll
        for (int kc = 0; kc < 4; kc++) {
            const int e0 = ((2 * kc) ^ g) << 2;
            const int e1 = ((2 * kc + 1) ^ g) << 2;
            const uint32_t bh0 = sWh[rbase + e0], bh1 = sWh[rbase + e1];
            const uint32_t bl0 = sWl[rbase + e0], bl1 = sWl[rbase + e1];
            MMA16816(D[jj][0],D[jj][1],D[jj][2],D[jj][3], ah[4*kc],ah[4*kc+1],ah[4*kc+2],ah[4*kc+3], bh0,bh1);
            MMA16816(D[jj][0],D[jj][1],D[jj][2],D[jj][3], al[4*kc],al[4*kc+1],al[4*kc+2],al[4*kc+3], bh0,bh1);
            MMA16816(D[jj][0],D[jj][1],D[jj][2],D[jj][3], ah[4*kc],ah[4*kc+1],ah[4*kc+2],ah[4*kc+3], bl0,bl1);
        }
    }

    // ---- epilogue ----
    const int rg  = rows_base + (wid & 3) * 16 + g;
    const int rg8 = rg + 8;
    const int b = rg >> 12, t0 = rg & (T_ - 1), t8 = t0 + 8;

#pragma unroll
    for (int jj = 0; jj < 12; jj++) {
        const int j = nh * 12 + jj;
        const int h = 8 * (j & 7) + 2 * tq;
        float v0 = D[jj][0], v1 = D[jj][1], v2 = D[jj][2], v3 = D[jj][3];
        if (j < 8) { v0 *= 8.f; v1 *= 8.f; v2 *= 8.f; v3 *= 8.f; }   // Q * C**0.5
        const __half2 hA = __floats2half2_rn(v0, v1);
        const __half2 hB = __floats2half2_rn(v2, v3);
        const __half2 lA = __floats2half2_rn(v0 - __half2float(__low2half(hA)),
                                             v1 - __half2float(__high2half(hA)));
        const __half2 lB = __floats2half2_rn(v2 - __half2float(__low2half(hB)),
                                             v3 - __half2float(__high2half(hB)));
        if (j < 8) {
            *(uint32_t*)&g_qh[(size_t)rg  * 64 + h] = h2u(hA);
            *(uint32_t*)&g_qh[(size_t)rg8 * 64 + h] = h2u(hB);
            *(uint32_t*)&g_ql[(size_t)rg  * 64 + h] = h2u(lA);
            *(uint32_t*)&g_ql[(size_t)rg8 * 64 + h] = h2u(lB);
        } else if (j < 16) {
            *(uint32_t*)&g_kh[(size_t)rg  * 64 + h] = h2u(hA);
            *(uint32_t*)&g_kh[(size_t)rg8 * 64 + h] = h2u(hB);
            *(uint32_t*)&g_kl[(size_t)rg  * 64 + h] = h2u(lA);
            *(uint32_t*)&g_kl[(size_t)rg8 * 64 + h] = h2u(lB);
        } else {
            const size_t r0 = ((size_t)b * 64 + h) * T_;
            const size_t r1 = ((size_t)b * 64 + h + 1) * T_;
            g_vh[r0 + t0] = __low2half(hA);  g_vh[r1 + t0] = __high2half(hA);
            g_vh[r0 + t8] = __low2half(hB);  g_vh[r1 + t8] = __high2half(hB);
            g_vl[r0 + t0] = __low2half(lA);  g_vl[r1 + t0] = __high2half(lA);
            g_vl[r0 + t8] = __low2half(lB);  g_vl[r1 + t8] = __high2half(lB);
        }
    }
}

// ---------------- Kernel 2: FA2-style mma.sync flash attention (split-K partials)
// SMEM: 2 x 32KB K/V double buffer + 32KB Q (hi/lo) = 96KB/CTA, 2 CTAs/SM.
#define ABYTES 8192
#define BUFBYTES (4 * ABYTES)
#define QH_OFF 65536
#define QL_OFF 81920
#define SMEM_BYTES 98304

extern __shared__ char dsm[];

__device__ __forceinline__ void copy_tile(int b, int k0, int buf, int tid, uint32_t smb)
{
#pragma unroll
    for (int i = 0; i < 8; i++) {
        const int id = tid + i * 256;           // 0..2047
        const int arr = id >> 9;                // 0..3 (uniform per i-range)
        const int r = (id >> 3) & 63;
        const int ch = id & 7;
        const uint32_t dst = smb + buf * BUFBYTES + arr * ABYTES + r * 128 + ((ch ^ (r & 7)) << 4);
        const __half* src;
        if (arr == 0)      src = g_kh + ((size_t)(b * T_ + k0 + r)) * 64 + ch * 8;
        else if (arr == 1) src = g_kl + ((size_t)(b * T_ + k0 + r)) * 64 + ch * 8;
        else if (arr == 2) src = g_vh + ((size_t)(b * 64 + r)) * T_ + k0 + ch * 8;
        else               src = g_vl + ((size_t)(b * 64 + r)) * T_ + k0 + ch * 8;
        CP_ASYNC16(dst, src);
    }
}

__device__ __forceinline__ void copy_q(int b, int q0, int tid, uint32_t smb)
{
#pragma unroll
    for (int i = 0; i < 8; i++) {
        const int id = tid + i * 256;           // 0..2047
        const int arr = id >> 10;               // 0=qh, 1=ql
        const int r = (id >> 3) & 127;
        const int ch = id & 7;
        const uint32_t dst = smb + QH_OFF + arr * 16384 + r * 128 + ((ch ^ (r & 7)) << 4);
        const __half* src = (arr == 0 ? g_qh : g_ql) + ((size_t)(b * T_ + q0 + r)) * 64 + ch * 8;
        CP_ASYNC16(dst, src);
    }
}

__global__ __launch_bounds__(256, 2) void attn_kernel()
{
    const int b = blockIdx.y;
    // heavy-first (t, c) mapping: q-tile t has t/8+1 chunks; sum = 80
    int u = blockIdx.x, t = 0, c = 0;
#pragma unroll 1
    for (int tt = 31; tt >= 0; tt--) { int n = tt / 8 + 1; if (u < n) { t = tt; c = u; break; } u -= n; }
    const int q0 = t * BM, k0c = c * KC;
    const int kend = min(k0c + KC, (t + 1) * BM);
    const int nT = (kend - k0c) / KN;

    const int tid = threadIdx.x, wid = tid >> 5, lane = tid & 31;
    const int g = lane >> 2, tq = lane & 3;
    const int qi0 = q0 + wid * 16;
    const int rg = qi0 + g, rg8 = rg + 8;
    const uint32_t smb = smem_u32(dsm);

    float O[8][4];
#pragma unroll
    for (int j = 0; j < 8; j++) { O[j][0]=0.f; O[j][1]=0.f; O[j][2]=0.f; O[j][3]=0.f; }
    float m0 = -1e30f, m1 = -1e30f, l0 = 0.f, l1 = 0.f;

    copy_q(b, q0, tid, smb);
    copy_tile(b, k0c, 0, tid, smb);
    CP_COMMIT();

    const uint32_t* sQh = (const uint32_t*)(dsm + QH_OFF);
    const uint32_t* sQl = (const uint32_t*)(dsm + QL_OFF);
    const int rbQ  = (wid * 16 + g) * 32 + tq;
    const int rbQ8 = rbQ + 256;

    for (int n = 0; n < nT; n++) {
        const int k0 = k0c + n * KN;
        const int buf = n & 1;
        __syncthreads();                          // prev compute done before overwrite
        if (n + 1 < nT) { copy_tile(b, k0 + KN, (n + 1) & 1, tid, smb); CP_COMMIT(); CP_WAIT(1); }
        else            { CP_WAIT(0); }
        __syncthreads();                          // tile n (and Q) visible to all

        const uint32_t* sKh = (const uint32_t*)(dsm + buf * BUFBYTES);
        const uint32_t* sKl = (const uint32_t*)(dsm + buf * BUFBYTES + ABYTES);
        const uint32_t* sVh = (const uint32_t*)(dsm + buf * BUFBYTES + 2 * ABYTES);
        const uint32_t* sVl = (const uint32_t*)(dsm + buf * BUFBYTES + 3 * ABYTES);

        // ---- S = Q·K^T (3-term hi/lo); kc outer so only 8 A-regs live ----
        float SD[8][4];
#pragma unroll
        for (int j = 0; j < 8; j++) { SD[j][0]=0.f; SD[j][1]=0.f; SD[j][2]=0.f; SD[j][3]=0.f; }
#pragma unroll
        for (int kc = 0; kc < 4; kc++) {
            const int e0 = ((2 * kc) ^ g) << 2;
            const int e1 = ((2 * kc + 1) ^ g) << 2;
            const uint32_t a0 = sQh[rbQ + e0], a1 = sQh[rbQ8 + e0];
            const uint32_t a2 = sQh[rbQ + e1], a3 = sQh[rbQ8 + e1];
            const uint32_t c0r = sQl[rbQ + e0], c1r = sQl[rbQ8 + e0];
            const uint32_t c2r = sQl[rbQ + e1], c3r = sQl[rbQ8 + e1];
#pragma unroll
            for (int j = 0; j < 8; j++) {
                const int rbase = (8 * j + g) * 32 + tq;
                const uint32_t bh0 = sKh[rbase + e0], bh1 = sKh[rbase + e1];
                const uint32_t bl0 = sKl[rbase + e0], bl1 = sKl[rbase + e1];
                MMA16816(SD[j][0],SD[j][1],SD[j][2],SD[j][3], a0,a1,a2,a3, bh0,bh1);
                MMA16816(SD[j][0],SD[j][1],SD[j][2],SD[j][3], c0r,c1r,c2r,c3r, bh0,bh1);
                MMA16816(SD[j][0],SD[j][1],SD[j][2],SD[j][3], a0,a1,a2,a3, bl0,bl1);
            }
        }

        // ---- causal mask (warp-uniform predicate) ----
        if (k0 + KN - 1 > qi0) {
#pragma unroll
            for (int j = 0; j < 8; j++) {
                const int col = k0 + 8 * j + 2 * tq;
                if (col     > rg)  SD[j][0] = -1e30f;
                if (col + 1 > rg)  SD[j][1] = -1e30f;
                if (col     > rg8) SD[j][2] = -1e30f;
                if (col + 1 > rg8) SD[j][3] = -1e30f;
            }
        }

        // ---- online softmax ----
        float bm0 = -1e30f, bm1 = -1e30f;
#pragma unroll
        for (int j = 0; j < 8; j++) {
            bm0 = fmaxf(bm0, fmaxf(SD[j][0], SD[j][1]));
            bm1 = fmaxf(bm1, fmaxf(SD[j][2], SD[j][3]));
        }
        bm0 = fmaxf(bm0, __shfl_xor_sync(0xFFFFFFFFu, bm0, 1));
        bm0 = fmaxf(bm0, __shfl_xor_sync(0xFFFFFFFFu, bm0, 2));
        bm1 = fmaxf(bm1, __shfl_xor_sync(0xFFFFFFFFu, bm1, 1));
        bm1 = fmaxf(bm1, __shfl_xor_sync(0xFFFFFFFFu, bm1, 2));
        const float mn0 = fmaxf(m0, bm0), mn1 = fmaxf(m1, bm1);
        const float c0 = __expf(m0 - mn0), c1 = __expf(m1 - mn1);

        float s0 = 0.f, s1 = 0.f;
#pragma unroll
        for (int j = 0; j < 8; j++) {
            SD[j][0] = __expf(SD[j][0] - mn0);
            SD[j][1] = __expf(SD[j][1] - mn0);
            SD[j][2] = __expf(SD[j][2] - mn1);
            SD[j][3] = __expf(SD[j][3] - mn1);
            s0 += SD[j][0] + SD[j][1];
            s1 += SD[j][2] + SD[j][3];
        }
        s0 += __shfl_xor_sync(0xFFFFFFFFu, s0, 1);
        s0 += __shfl_xor_sync(0xFFFFFFFFu, s0, 2);
        s1 += __shfl_xor_sync(0xFFFFFFFFu, s1, 1);
        s1 += __shfl_xor_sync(0xFFFFFFFFu, s1, 2);
        l0 = fmaf(l0, c0, s0);
        l1 = fmaf(l1, c1, s1);
        m0 = mn0; m1 = mn1;

#pragma unroll
        for (int j = 0; j < 8; j++) {
            O[j][0] *= c0; O[j][1] *= c0; O[j][2] *= c1; O[j][3] *= c1;
        }

        // ---- O += P·V (2-term: ph*vh + ph*vl) ----
#pragma unroll
        for (int kc = 0; kc < 4; kc++) {
            __half2 h0 = __floats2half2_rn(SD[2*kc][0],   SD[2*kc][1]);
            __half2 h1 = __floats2half2_rn(SD[2*kc][2],   SD[2*kc][3]);
            __half2 h2 = __floats2half2_rn(SD[2*kc+1][0], SD[2*kc+1][1]);
            __half2 h3 = __floats2half2_rn(SD[2*kc+1][2], SD[2*kc+1][3]);
            const uint32_t pa0 = h2u(h0), pa1 = h2u(h1);
            const uint32_t pa2 = h2u(h2), pa3 = h2u(h3);
            const int ee0 = ((2 * kc) ^ g) << 2;
            const int ee1 = ((2 * kc + 1) ^ g) << 2;
#pragma unroll
            for (int j = 0; j < 8; j++) {
                const int rbase = (8 * j + g) * 32 + tq;
                const uint32_t vh0 = sVh[rbase + ee0], vh1 = sVh[rbase + ee1];
                const uint32_t vl0 = sVl[rbase + ee0], vl1 = sVl[rbase + ee1];
                MMA16816(O[j][0],O[j][1],O[j][2],O[j][3], pa0,pa1,pa2,pa3, vh0,vh1);
                MMA16816(O[j][0],O[j][1],O[j][2],O[j][3], pa0,pa1,pa2,pa3, vl0,vl1);
            }
        }
    }

    // ---- write partials ----
    const size_t p0 = ((size_t)(b * T_ + rg)) * NCMAX + c;
    const size_t p1 = ((size_t)(b * T_ + rg8)) * NCMAX + c;
    if (tq == 0) {
        g_pm[p0] = m0; g_pl[p0] = l0;
        g_pm[p1] = m1; g_pl[p1] = l1;
    }
#pragma unroll
    for (int j = 0; j < 8; j++) {
        float2 a; a.x = O[j][0]; a.y = O[j][1];
        float2 d; d.x = O[j][2]; d.y = O[j][3];
        *(float2*)&g_po[p0 * 64 + 8 * j + 2 * tq] = a;
        *(float2*)&g_po[p1 * 64 + 8 * j + 2 * tq] = d;
    }
}

// ---------------- Kernel 3: merge split-K partials
__global__ __launch_bounds__(128) void attn_reduce_kernel(float* __restrict__ out)
{
    const int gid = blockIdx.x * 128 + threadIdx.x;
    const int qi = gid & (T_ - 1);
    const int nc = (qi >> 7) / 8 + 1;
    const size_t pbase = (size_t)gid * NCMAX;

    float m = -1e30f;
    for (int cc = 0; cc < nc; cc++) m = fmaxf(m, g_pm[pbase + cc]);
    float l = 0.f;
    float o[HS_];
#pragma unroll
    for (int i = 0; i < HS_; i++) o[i] = 0.f;
    for (int cc = 0; cc < nc; cc++) {
        const float w = __expf(g_pm[pbase + cc] - m);
        l = fmaf(g_pl[pbase + cc], w, l);
        const float4* pp = reinterpret_cast<const float4*>(g_po + (pbase + cc) * HS_);
#pragma unroll
        for (int i = 0; i < 16; i++) {
            float4 v = pp[i];
            o[4*i]   = fmaf(w, v.x, o[4*i]);
            o[4*i+1] = fmaf(w, v.y, o[4*i+1]);
            o[4*i+2] = fmaf(w, v.z, o[4*i+2]);
            o[4*i+3] = fmaf(w, v.w, o[4*i+3]);
        }
    }
    const float inv = 1.0f / l;
    float4* op = reinterpret_cast<float4*>(out + (size_t)gid * HS_);
#pragma unroll
    for (int i = 0; i < 16; i++) {
        float4 v;
        v.x = o[4*i] * inv;   v.y = o[4*i+1] * inv;
        v.z = o[4*i+2] * inv; v.w = o[4*i+3] * inv;
        op[i] = v;
    }
}

// ---------------------------------------------------------------------------
extern "C" void kernel_launch(void* const* d_in, const int* in_sizes, int n_in,
                              void* d_out, int out_size)
{
    const float* x  = (const float*)d_in[0];
    const float* Wq = (const float*)d_in[1];
    const float* Wk = (const float*)d_in[2];
    const float* Wv = (const float*)d_in[3];
    float* out = (float*)d_out;

    cudaFuncSetAttribute(proj_kernel, cudaFuncAttributeMaxDynamicSharedMemorySize, PROJ_SMEM);
    cudaFuncSetAttribute(attn_kernel, cudaFuncAttributeMaxDynamicSharedMemorySize, SMEM_BYTES);

    wconv_kernel<<<6, 256>>>(Wq, Wk, Wv);
    proj_kernel<<<(B_ * T_) / 64, 256, PROJ_SMEM>>>(x);

    dim3 ag(80, B_);
    attn_kernel<<<ag, 256, SMEM_BYTES>>>();

    attn_reduce_kernel<<<(B_ * T_) / 128, 128>>>(out);
}

// round 10
// speedup vs baseline: 7.8274x; 1.0987x over previous
#include <cuda_runtime.h>
#include <cuda_fp16.h>
#include <cstdint>

#define B_ 4
#define T_ 4096
#define HS_ 64
#define BM 128
#define KN 64
#define KC 1024
#define NCMAX 4

// Device scratch (no cudaMalloc allowed). 16B-aligned for vector/cp.async access.
__device__ __align__(16) __half g_qh[B_*T_*HS_], g_ql[B_*T_*HS_];
__device__ __align__(16) __half g_kh[B_*T_*HS_], g_kl[B_*T_*HS_];
__device__ __align__(16) __half g_vh[B_*HS_*T_], g_vl[B_*HS_*T_];   // V^T: [b][h][t]
__device__ __align__(16) __half g_wh[192*64], g_wl[192*64];         // stacked [Wq;Wk;Wv]^T
__device__ float g_pm[B_*T_*NCMAX], g_pl[B_*T_*NCMAX];
__device__ float g_po[(size_t)B_*T_*NCMAX*HS_];

// ---------------- PTX helpers (family-agnostic: sm_80+) ----------------
__device__ __forceinline__ uint32_t smem_u32(const void* p) {
    uint32_t a;
    asm("{ .reg .u64 t; cvta.to.shared.u64 t, %1; cvt.u32.u64 %0, t; }" : "=r"(a) : "l"(p));
    return a;
}
#define CP_ASYNC16(dst, src) \
    asm volatile("cp.async.cg.shared.global [%0], [%1], 16;" :: "r"(dst), "l"(src))
#define CP_COMMIT() asm volatile("cp.async.commit_group;" ::: "memory")
#define CP_WAIT(n)  asm volatile("cp.async.wait_group %0;" :: "n"(n) : "memory")

// D(16x8,f32) += A(16x16,f16) * B(16x8,f16)   row.col
#define MMA16816(D0,D1,D2,D3, A0,A1,A2,A3, B0,B1) \
    asm volatile("mma.sync.aligned.m16n8k16.row.col.f32.f16.f16.f32 " \
        "{%0,%1,%2,%3}, {%4,%5,%6,%7}, {%8,%9}, {%0,%1,%2,%3};" \
        : "+f"(D0), "+f"(D1), "+f"(D2), "+f"(D3) \
        : "r"(A0), "r"(A1), "r"(A2), "r"(A3), "r"(B0), "r"(B1))

#define LDSM4(R0,R1,R2,R3, ADDR) \
    asm volatile("ldmatrix.sync.aligned.m8n8.x4.shared.b16 {%0,%1,%2,%3}, [%4];" \
        : "=r"(R0), "=r"(R1), "=r"(R2), "=r"(R3) : "r"(ADDR))

__device__ __forceinline__ uint32_t h2u(__half2 h) { return *(uint32_t*)&h; }

// ---------------- Kernel 0: W -> fp16 hi/lo, stacked [n=mat*64+h][k=d] ----------------
__global__ __launch_bounds__(256) void wconv_kernel(
    const float* __restrict__ Wq, const float* __restrict__ Wk, const float* __restrict__ Wv)
{
    const int id = blockIdx.x * 256 + threadIdx.x;    // 0..1535
    const int n = id >> 3, ch = id & 7;
    const int m = n >> 6, h = n & 63;
    const float* W = m == 0 ? Wq : (m == 1 ? Wk : Wv);
    float f[8];
#pragma unroll
    for (int dd = 0; dd < 8; dd++) f[dd] = W[(ch * 8 + dd) * 64 + h];
    uint4 hi, lo;
    uint32_t* hp = &hi.x;
    uint32_t* lp = &lo.x;
#pragma unroll
    for (int p = 0; p < 4; p++) {
        __half2 a = __floats2half2_rn(f[2*p], f[2*p+1]);
        hp[p] = h2u(a);
        __half2 bq = __floats2half2_rn(f[2*p]   - __half2float(__low2half(a)),
                                       f[2*p+1] - __half2float(__high2half(a)));
        lp[p] = h2u(bq);
    }
    *reinterpret_cast<uint4*>(&g_wh[n * 64 + ch * 8]) = hi;
    *reinterpret_cast<uint4*>(&g_wl[n * 64 + ch * 8]) = lo;
}

// ---------------- Kernel 1: tensor-core QKV projection ----------------
#define XA_H 0
#define XA_L 8192
#define WW_H 16384
#define WW_L 40960
#define PROJ_SMEM 65536

extern __shared__ char psm[];

__global__ __launch_bounds__(256, 2) void proj_kernel(const float* __restrict__ x)
{
    const int tid = threadIdx.x;
    const int wid = tid >> 5, lane = tid & 31;
    const int g = lane >> 2, tq = lane & 3;
    const int rows_base = blockIdx.x * 64;
    const uint32_t smb = smem_u32(psm);

    // ---- W tiles via cp.async (coalesced, L2-resident) ----
#pragma unroll
    for (int it = 0; it < 6; it++) {
        const int id = tid + it * 256;            // 0..1535
        const int n = id >> 3, ch = id & 7;
        const uint32_t off = n * 128 + ((ch ^ (n & 7)) << 4);
        CP_ASYNC16(smb + WW_H + off, g_wh + n * 64 + ch * 8);
        CP_ASYNC16(smb + WW_L + off, g_wl + n * 64 + ch * 8);
    }
    CP_COMMIT();

    // ---- x tile: fp32 -> fp16 hi/lo (through regs) ----
#pragma unroll
    for (int it = 0; it < 2; it++) {
        const int id = tid + it * 256;            // 0..511
        const int r = id >> 3, ch = id & 7;
        const float4* xp = reinterpret_cast<const float4*>(
            x + ((size_t)(rows_base + r)) * 64 + ch * 8);
        const float4 f0 = xp[0], f1 = xp[1];
        uint4 hi, lo;
        __half2 a, bq;
        a = __floats2half2_rn(f0.x, f0.y); hi.x = h2u(a);
        bq = __floats2half2_rn(f0.x - __half2float(__low2half(a)), f0.y - __half2float(__high2half(a))); lo.x = h2u(bq);
        a = __floats2half2_rn(f0.z, f0.w); hi.y = h2u(a);
        bq = __floats2half2_rn(f0.z - __half2float(__low2half(a)), f0.w - __half2float(__high2half(a))); lo.y = h2u(bq);
        a = __floats2half2_rn(f1.x, f1.y); hi.z = h2u(a);
        bq = __floats2half2_rn(f1.x - __half2float(__low2half(a)), f1.y - __half2float(__high2half(a))); lo.z = h2u(bq);
        a = __floats2half2_rn(f1.z, f1.w); hi.w = h2u(a);
        bq = __floats2half2_rn(f1.z - __half2float(__low2half(a)), f1.w - __half2float(__high2half(a))); lo.w = h2u(bq);
        const uint32_t off = r * 128 + ((ch ^ (r & 7)) << 4);
        *reinterpret_cast<uint4*>(psm + XA_H + off) = hi;
        *reinterpret_cast<uint4*>(psm + XA_L + off) = lo;
    }
    CP_WAIT(0);
    __syncthreads();

    const uint32_t* sAh = (const uint32_t*)(psm + XA_H);
    const uint32_t* sAl = (const uint32_t*)(psm + XA_L);
    const uint32_t* sWh = (const uint32_t*)(psm + WW_H);
    const uint32_t* sWl = (const uint32_t*)(psm + WW_L);

    uint32_t ah[16], al[16];
    {
        const int rb  = ((wid & 3) * 16 + g) * 32 + tq;
        const int rb8 = rb + 256;
#pragma unroll
        for (int kc = 0; kc < 4; kc++) {
            const int e0 = ((2 * kc) ^ g) << 2;
            const int e1 = ((2 * kc + 1) ^ g) << 2;
            ah[4*kc+0] = sAh[rb + e0];  ah[4*kc+1] = sAh[rb8 + e0];
            ah[4*kc+2] = sAh[rb + e1];  ah[4*kc+3] = sAh[rb8 + e1];
            al[4*kc+0] = sAl[rb + e0];  al[4*kc+1] = sAl[rb8 + e0];
            al[4*kc+2] = sAl[rb + e1];  al[4*kc+3] = sAl[rb8 + e1];
        }
    }

    const int nh = wid >> 2;                      // n-half: 0 or 1
    float D[12][4];
#pragma unroll
    for (int j = 0; j < 12; j++) { D[j][0]=0.f; D[j][1]=0.f; D[j][2]=0.f; D[j][3]=0.f; }

#pragma unroll
    for (int jj = 0; jj < 12; jj++) {
        const int jg = nh * 12 + jj;
        const int rbase = (8 * jg + g) * 32 + tq;
#pragma unroll
        for (int kc = 0; kc < 4; kc++) {
            const int e0 = ((2 * kc) ^ g) << 2;
            const int e1 = ((2 * kc + 1) ^ g) << 2;
            const uint32_t bh0 = sWh[rbase + e0], bh1 = sWh[rbase + e1];
            const uint32_t bl0 = sWl[rbase + e0], bl1 = sWl[rbase + e1];
            MMA16816(D[jj][0],D[jj][1],D[jj][2],D[jj][3], ah[4*kc],ah[4*kc+1],ah[4*kc+2],ah[4*kc+3], bh0,bh1);
            MMA16816(D[jj][0],D[jj][1],D[jj][2],D[jj][3], al[4*kc],al[4*kc+1],al[4*kc+2],al[4*kc+3], bh0,bh1);
            MMA16816(D[jj][0],D[jj][1],D[jj][2],D[jj][3], ah[4*kc],ah[4*kc+1],ah[4*kc+2],ah[4*kc+3], bl0,bl1);
        }
    }

    // ---- epilogue ----
    const int rg  = rows_base + (wid & 3) * 16 + g;
    const int rg8 = rg + 8;
    const int b = rg >> 12, t0 = rg & (T_ - 1), t8 = t0 + 8;

#pragma unroll
    for (int jj = 0; jj < 12; jj++) {
        const int j = nh * 12 + jj;
        const int h = 8 * (j & 7) + 2 * tq;
        float v0 = D[jj][0], v1 = D[jj][1], v2 = D[jj][2], v3 = D[jj][3];
        if (j < 8) { v0 *= 8.f; v1 *= 8.f; v2 *= 8.f; v3 *= 8.f; }   // Q * C**0.5
        const __half2 hA = __floats2half2_rn(v0, v1);
        const __half2 hB = __floats2half2_rn(v2, v3);
        const __half2 lA = __floats2half2_rn(v0 - __half2float(__low2half(hA)),
                                             v1 - __half2float(__high2half(hA)));
        const __half2 lB = __floats2half2_rn(v2 - __half2float(__low2half(hB)),
                                             v3 - __half2float(__high2half(hB)));
        if (j < 8) {
            *(uint32_t*)&g_qh[(size_t)rg  * 64 + h] = h2u(hA);
            *(uint32_t*)&g_qh[(size_t)rg8 * 64 + h] = h2u(hB);
            *(uint32_t*)&g_ql[(size_t)rg  * 64 + h] = h2u(lA);
            *(uint32_t*)&g_ql[(size_t)rg8 * 64 + h] = h2u(lB);
        } else if (j < 16) {
            *(uint32_t*)&g_kh[(size_t)rg  * 64 + h] = h2u(hA);
            *(uint32_t*)&g_kh[(size_t)rg8 * 64 + h] = h2u(hB);
            *(uint32_t*)&g_kl[(size_t)rg  * 64 + h] = h2u(lA);
            *(uint32_t*)&g_kl[(size_t)rg8 * 64 + h] = h2u(lB);
        } else {
            const size_t r0 = ((size_t)b * 64 + h) * T_;
            const size_t r1 = ((size_t)b * 64 + h + 1) * T_;
            g_vh[r0 + t0] = __low2half(hA);  g_vh[r1 + t0] = __high2half(hA);
            g_vh[r0 + t8] = __low2half(hB);  g_vh[r1 + t8] = __high2half(hB);
            g_vl[r0 + t0] = __low2half(lA);  g_vl[r1 + t0] = __high2half(lA);
            g_vl[r0 + t8] = __low2half(lB);  g_vl[r1 + t8] = __high2half(lB);
        }
    }
}

// ---------------- Kernel 2: FA2-style mma.sync flash attention (split-K partials)
// SMEM: 2 x 32KB K/V double buffer + 32KB Q (hi/lo) = 96KB/CTA, 2 CTAs/SM.
#define ABYTES 8192
#define BUFBYTES (4 * ABYTES)
#define QH_OFF 65536
#define QL_OFF 81920
#define SMEM_BYTES 98304

extern __shared__ char dsm[];

__device__ __forceinline__ void copy_tile(int b, int k0, int buf, int tid, uint32_t smb)
{
#pragma unroll
    for (int i = 0; i < 8; i++) {
        const int id = tid + i * 256;           // 0..2047
        const int arr = id >> 9;                // 0..3 (uniform per i-range)
        const int r = (id >> 3) & 63;
        const int ch = id & 7;
        const uint32_t dst = smb + buf * BUFBYTES + arr * ABYTES + r * 128 + ((ch ^ (r & 7)) << 4);
        const __half* src;
        if (arr == 0)      src = g_kh + ((size_t)(b * T_ + k0 + r)) * 64 + ch * 8;
        else if (arr == 1) src = g_kl + ((size_t)(b * T_ + k0 + r)) * 64 + ch * 8;
        else if (arr == 2) src = g_vh + ((size_t)(b * 64 + r)) * T_ + k0 + ch * 8;
        else               src = g_vl + ((size_t)(b * 64 + r)) * T_ + k0 + ch * 8;
        CP_ASYNC16(dst, src);
    }
}

__device__ __forceinline__ void copy_q(int b, int q0, int tid, uint32_t smb)
{
#pragma unroll
    for (int i = 0; i < 8; i++) {
        const int id = tid + i * 256;           // 0..2047
        const int arr = id >> 10;               // 0=qh, 1=ql
        const int r = (id >> 3) & 127;
        const int ch = id & 7;
        const uint32_t dst = smb + QH_OFF + arr * 16384 + r * 128 + ((ch ^ (r & 7)) << 4);
        const __half* src = (arr == 0 ? g_qh : g_ql) + ((size_t)(b * T_ + q0 + r)) * 64 + ch * 8;
        CP_ASYNC16(dst, src);
    }
}

__global__ __launch_bounds__(256, 2) void attn_kernel()
{
    const int b = blockIdx.y;
    // heavy-first (t, c) mapping: q-tile t has t/8+1 chunks; sum = 80
    int u = blockIdx.x, t = 0, c = 0;
#pragma unroll 1
    for (int tt = 31; tt >= 0; tt--) { int n = tt / 8 + 1; if (u < n) { t = tt; c = u; break; } u -= n; }
    const int q0 = t * BM, k0c = c * KC;
    const int kend = min(k0c + KC, (t + 1) * BM);
    const int nT = (kend - k0c) / KN;

    const int tid = threadIdx.x, wid = tid >> 5, lane = tid & 31;
    const int g = lane >> 2, tq = lane & 3;
    const int qi0 = q0 + wid * 16;
    const int rg = qi0 + g, rg8 = rg + 8;
    const uint32_t smb = smem_u32(dsm);

    // ldmatrix lane decomposition
    const int lr = lane & 7, q2 = lane >> 3;
    const uint32_t kv_row = (uint32_t)(((q2 >> 1) * 8 + lr) * 128);   // K/V: m-pair row offset
    const int eKV = q2 & 1;                                           // K/V: which k-chunk
    const uint32_t q_row = (uint32_t)((wid * 16 + (q2 & 1) * 8 + lr) * 128);  // Q rows
    const int eQ = q2 >> 1;

    float O[8][4];
#pragma unroll
    for (int j = 0; j < 8; j++) { O[j][0]=0.f; O[j][1]=0.f; O[j][2]=0.f; O[j][3]=0.f; }
    float m0 = -1e30f, m1 = -1e30f, l0 = 0.f, l1 = 0.f;

    copy_q(b, q0, tid, smb);
    copy_tile(b, k0c, 0, tid, smb);
    CP_COMMIT();

    for (int n = 0; n < nT; n++) {
        const int k0 = k0c + n * KN;
        const int buf = n & 1;
        __syncthreads();                          // prev compute done before overwrite
        if (n + 1 < nT) { copy_tile(b, k0 + KN, (n + 1) & 1, tid, smb); CP_COMMIT(); CP_WAIT(1); }
        else            { CP_WAIT(0); }
        __syncthreads();                          // tile n (and Q) visible to all

        const uint32_t kh_base = smb + buf * BUFBYTES + kv_row;
        const uint32_t vh_base = kh_base + 2 * ABYTES;

        // ---- S = Q·K^T (3-term hi/lo), ldmatrix fragment loads ----
        float SD[8][4];
#pragma unroll
        for (int j = 0; j < 8; j++) { SD[j][0]=0.f; SD[j][1]=0.f; SD[j][2]=0.f; SD[j][3]=0.f; }
#pragma unroll
        for (int kc = 0; kc < 4; kc++) {
            const uint32_t chQ = (uint32_t)(((2 * kc + eQ) ^ lr) << 4);
            uint32_t a0, a1, a2, a3, c0r, c1r, c2r, c3r;
            LDSM4(a0, a1, a2, a3, smb + QH_OFF + q_row + chQ);
            LDSM4(c0r, c1r, c2r, c3r, smb + QL_OFF + q_row + chQ);
            const uint32_t chK = (uint32_t)(((2 * kc + eKV) ^ lr) << 4);
#pragma unroll
            for (int j0 = 0; j0 < 8; j0 += 2) {
                uint32_t bh0, bh1, bh2, bh3, bl0, bl1, bl2, bl3;
                LDSM4(bh0, bh1, bh2, bh3, kh_base + chK + j0 * 1024);
                LDSM4(bl0, bl1, bl2, bl3, kh_base + ABYTES + chK + j0 * 1024);
                MMA16816(SD[j0][0],SD[j0][1],SD[j0][2],SD[j0][3], a0,a1,a2,a3, bh0,bh1);
                MMA16816(SD[j0][0],SD[j0][1],SD[j0][2],SD[j0][3], c0r,c1r,c2r,c3r, bh0,bh1);
                MMA16816(SD[j0][0],SD[j0][1],SD[j0][2],SD[j0][3], a0,a1,a2,a3, bl0,bl1);
                MMA16816(SD[j0+1][0],SD[j0+1][1],SD[j0+1][2],SD[j0+1][3], a0,a1,a2,a3, bh2,bh3);
                MMA16816(SD[j0+1][0],SD[j0+1][1],SD[j0+1][2],SD[j0+1][3], c0r,c1r,c2r,c3r, bh2,bh3);
                MMA16816(SD[j0+1][0],SD[j0+1][1],SD[j0+1][2],SD[j0+1][3], a0,a1,a2,a3, bl2,bl3);
            }
        }

        // ---- causal mask (warp-uniform predicate) ----
        if (k0 + KN - 1 > qi0) {
#pragma unroll
            for (int j = 0; j < 8; j++) {
                const int col = k0 + 8 * j + 2 * tq;
                if (col     > rg)  SD[j][0] = -1e30f;
                if (col + 1 > rg)  SD[j][1] = -1e30f;
                if (col     > rg8) SD[j][2] = -1e30f;
                if (col + 1 > rg8) SD[j][3] = -1e30f;
            }
        }

        // ---- online softmax ----
        float bm0 = -1e30f, bm1 = -1e30f;
#pragma unroll
        for (int j = 0; j < 8; j++) {
            bm0 = fmaxf(bm0, fmaxf(SD[j][0], SD[j][1]));
            bm1 = fmaxf(bm1, fmaxf(SD[j][2], SD[j][3]));
        }
        bm0 = fmaxf(bm0, __shfl_xor_sync(0xFFFFFFFFu, bm0, 1));
        bm0 = fmaxf(bm0, __shfl_xor_sync(0xFFFFFFFFu, bm0, 2));
        bm1 = fmaxf(bm1, __shfl_xor_sync(0xFFFFFFFFu, bm1, 1));
        bm1 = fmaxf(bm1, __shfl_xor_sync(0xFFFFFFFFu, bm1, 2));
        const float mn0 = fmaxf(m0, bm0), mn1 = fmaxf(m1, bm1);
        const float c0 = __expf(m0 - mn0), c1 = __expf(m1 - mn1);

        float s0 = 0.f, s1 = 0.f;
#pragma unroll
        for (int j = 0; j < 8; j++) {
            SD[j][0] = __expf(SD[j][0] - mn0);
            SD[j][1] = __expf(SD[j][1] - mn0);
            SD[j][2] = __expf(SD[j][2] - mn1);
            SD[j][3] = __expf(SD[j][3] - mn1);
            s0 += SD[j][0] + SD[j][1];
            s1 += SD[j][2] + SD[j][3];
        }
        s0 += __shfl_xor_sync(0xFFFFFFFFu, s0, 1);
        s0 += __shfl_xor_sync(0xFFFFFFFFu, s0, 2);
        s1 += __shfl_xor_sync(0xFFFFFFFFu, s1, 1);
        s1 += __shfl_xor_sync(0xFFFFFFFFu, s1, 2);
        l0 = fmaf(l0, c0, s0);
        l1 = fmaf(l1, c1, s1);
        m0 = mn0; m1 = mn1;

#pragma unroll
        for (int j = 0; j < 8; j++) {
            O[j][0] *= c0; O[j][1] *= c0; O[j][2] *= c1; O[j][3] *= c1;
        }

        // ---- O += P·V (2-term: ph*vh + ph*vl), ldmatrix fragment loads ----
#pragma unroll
        for (int kc = 0; kc < 4; kc++) {
            __half2 h0 = __floats2half2_rn(SD[2*kc][0],   SD[2*kc][1]);
            __half2 h1 = __floats2half2_rn(SD[2*kc][2],   SD[2*kc][3]);
            __half2 h2 = __floats2half2_rn(SD[2*kc+1][0], SD[2*kc+1][1]);
            __half2 h3 = __floats2half2_rn(SD[2*kc+1][2], SD[2*kc+1][3]);
            const uint32_t pa0 = h2u(h0), pa1 = h2u(h1);
            const uint32_t pa2 = h2u(h2), pa3 = h2u(h3);
            const uint32_t chV = (uint32_t)(((2 * kc + eKV) ^ lr) << 4);
#pragma unroll
            for (int j0 = 0; j0 < 8; j0 += 2) {
                uint32_t vh0, vh1, vh2, vh3, vl0, vl1, vl2, vl3;
                LDSM4(vh0, vh1, vh2, vh3, vh_base + chV + j0 * 1024);
                LDSM4(vl0, vl1, vl2, vl3, vh_base + ABYTES + chV + j0 * 1024);
                MMA16816(O[j0][0],O[j0][1],O[j0][2],O[j0][3], pa0,pa1,pa2,pa3, vh0,vh1);
                MMA16816(O[j0][0],O[j0][1],O[j0][2],O[j0][3], pa0,pa1,pa2,pa3, vl0,vl1);
                MMA16816(O[j0+1][0],O[j0+1][1],O[j0+1][2],O[j0+1][3], pa0,pa1,pa2,pa3, vh2,vh3);
                MMA16816(O[j0+1][0],O[j0+1][1],O[j0+1][2],O[j0+1][3], pa0,pa1,pa2,pa3, vl2,vl3);
            }
        }
    }

    // ---- write partials ----
    const size_t p0 = ((size_t)(b * T_ + rg)) * NCMAX + c;
    const size_t p1 = ((size_t)(b * T_ + rg8)) * NCMAX + c;
    if (tq == 0) {
        g_pm[p0] = m0; g_pl[p0] = l0;
        g_pm[p1] = m1; g_pl[p1] = l1;
    }
#pragma unroll
    for (int j = 0; j < 8; j++) {
        float2 a; a.x = O[j][0]; a.y = O[j][1];
        float2 d; d.x = O[j][2]; d.y = O[j][3];
        *(float2*)&g_po[p0 * 64 + 8 * j + 2 * tq] = a;
        *(float2*)&g_po[p1 * 64 + 8 * j + 2 * tq] = d;
    }
}

// ---------------- Kernel 3: merge split-K partials (parallel: thread = (row, float4))
__global__ __launch_bounds__(256) void attn_reduce_kernel(float* __restrict__ out)
{
    const int gid2 = blockIdx.x * 256 + threadIdx.x;   // 0 .. B*T*16
    const int row = gid2 >> 4, part = gid2 & 15;
    const int qi = row & (T_ - 1);
    const int nc = (qi >> 7) / 8 + 1;
    const size_t pbase = (size_t)row * NCMAX;

    float m = -1e30f;
    for (int cc = 0; cc < nc; cc++) m = fmaxf(m, g_pm[pbase + cc]);

    float l = 0.f;
    float ox = 0.f, oy = 0.f, oz = 0.f, ow = 0.f;
    for (int cc = 0; cc < nc; cc++) {
        const float w = __expf(g_pm[pbase + cc] - m);
        l = fmaf(g_pl[pbase + cc], w, l);
        const float4 v = *reinterpret_cast<const float4*>(
            &g_po[(pbase + cc) * HS_ + part * 4]);
        ox = fmaf(w, v.x, ox); oy = fmaf(w, v.y, oy);
        oz = fmaf(w, v.z, oz); ow = fmaf(w, v.w, ow);
    }
    const float inv = 1.0f / l;
    float4 r;
    r.x = ox * inv; r.y = oy * inv; r.z = oz * inv; r.w = ow * inv;
    *reinterpret_cast<float4*>(&out[(size_t)row * HS_ + part * 4]) = r;
}

// ---------------------------------------------------------------------------
extern "C" void kernel_launch(void* const* d_in, const int* in_sizes, int n_in,
                              void* d_out, int out_size)
{
    const float* x  = (const float*)d_in[0];
    const float* Wq = (const float*)d_in[1];
    const float* Wk = (const float*)d_in[2];
    const float* Wv = (const float*)d_in[3];
    float* out = (float*)d_out;

    cudaFuncSetAttribute(proj_kernel, cudaFuncAttributeMaxDynamicSharedMemorySize, PROJ_SMEM);
    cudaFuncSetAttribute(attn_kernel, cudaFuncAttributeMaxDynamicSharedMemorySize, SMEM_BYTES);

    wconv_kernel<<<6, 256>>>(Wq, Wk, Wv);
    proj_kernel<<<(B_ * T_) / 64, 256, PROJ_SMEM>>>(x);

    dim3 ag(80, B_);
    attn_kernel<<<ag, 256, SMEM_BYTES>>>();

    attn_reduce_kernel<<<(B_ * T_ * 16) / 256, 256>>>(out);
}

// round 11
// speedup vs baseline: 8.3098x; 1.0616x over previous
#include <cuda_runtime.h>
#include <cuda_fp16.h>
#include <cstdint>

#define B_ 4
#define T_ 4096
#define HS_ 64
#define BM 128
#define KN 64
#define KC 1024
#define NCMAX 4

// Device scratch (no cudaMalloc allowed). 16B-aligned for vector/cp.async access.
__device__ __align__(16) __half g_qh[B_*T_*HS_], g_ql[B_*T_*HS_];
__device__ __align__(16) __half g_kh[B_*T_*HS_], g_kl[B_*T_*HS_];
__device__ __align__(16) __half g_vh[B_*HS_*T_], g_vl[B_*HS_*T_];   // V^T: [b][h][t]
__device__ __align__(16) __half g_wh[192*64], g_wl[192*64];         // stacked [Wq;Wk;Wv]^T
__device__ float g_pm[B_*T_*NCMAX], g_pl[B_*T_*NCMAX];              // m in log2 units
__device__ float g_po[(size_t)B_*T_*NCMAX*HS_];

// ---------------- PTX helpers (family-agnostic: sm_80+) ----------------
__device__ __forceinline__ uint32_t smem_u32(const void* p) {
    uint32_t a;
    asm("{ .reg .u64 t; cvta.to.shared.u64 t, %1; cvt.u32.u64 %0, t; }" : "=r"(a) : "l"(p));
    return a;
}
#define CP_ASYNC16(dst, src) \
    asm volatile("cp.async.cg.shared.global [%0], [%1], 16;" :: "r"(dst), "l"(src))
#define CP_COMMIT() asm volatile("cp.async.commit_group;" ::: "memory")
#define CP_WAIT(n)  asm volatile("cp.async.wait_group %0;" :: "n"(n) : "memory")

// D(16x8,f32) += A(16x16,f16) * B(16x8,f16)   row.col
#define MMA16816(D0,D1,D2,D3, A0,A1,A2,A3, B0,B1) \
    asm volatile("mma.sync.aligned.m16n8k16.row.col.f32.f16.f16.f32 " \
        "{%0,%1,%2,%3}, {%4,%5,%6,%7}, {%8,%9}, {%0,%1,%2,%3};" \
        : "+f"(D0), "+f"(D1), "+f"(D2), "+f"(D3) \
        : "r"(A0), "r"(A1), "r"(A2), "r"(A3), "r"(B0), "r"(B1))

#define LDSM4(R0,R1,R2,R3, ADDR) \
    asm volatile("ldmatrix.sync.aligned.m8n8.x4.shared.b16 {%0,%1,%2,%3}, [%4];" \
        : "=r"(R0), "=r"(R1), "=r"(R2), "=r"(R3) : "r"(ADDR))

__device__ __forceinline__ uint32_t h2u(__half2 h) { return *(uint32_t*)&h; }
__device__ __forceinline__ float ex2f(float x) {
    float r; asm("ex2.approx.f32 %0, %1;" : "=f"(r) : "f"(x)); return r;
}
__device__ __forceinline__ uint32_t ex2h2(uint32_t x) {
    uint32_t r; asm("ex2.approx.f16x2 %0, %1;" : "=r"(r) : "r"(x)); return r;
}
#define ONES16 0x3C003C00u   // half2(1.0, 1.0)

// Q scale: 8 (the reference's C**0.5) * log2(e) -> scores arrive in log2 units
#define QSCALE 11.5415603271117f

// ---------------- Kernel 0: W -> fp16 hi/lo, stacked [n=mat*64+h][k=d] ----------------
__global__ __launch_bounds__(256) void wconv_kernel(
    const float* __restrict__ Wq, const float* __restrict__ Wk, const float* __restrict__ Wv)
{
    const int id = blockIdx.x * 256 + threadIdx.x;    // 0..1535
    const int n = id >> 3, ch = id & 7;
    const int m = n >> 6, h = n & 63;
    const float* W = m == 0 ? Wq : (m == 1 ? Wk : Wv);
    float f[8];
#pragma unroll
    for (int dd = 0; dd < 8; dd++) f[dd] = W[(ch * 8 + dd) * 64 + h];
    uint4 hi, lo;
    uint32_t* hp = &hi.x;
    uint32_t* lp = &lo.x;
#pragma unroll
    for (int p = 0; p < 4; p++) {
        __half2 a = __floats2half2_rn(f[2*p], f[2*p+1]);
        hp[p] = h2u(a);
        __half2 bq = __floats2half2_rn(f[2*p]   - __half2float(__low2half(a)),
                                       f[2*p+1] - __half2float(__high2half(a)));
        lp[p] = h2u(bq);
    }
    *reinterpret_cast<uint4*>(&g_wh[n * 64 + ch * 8]) = hi;
    *reinterpret_cast<uint4*>(&g_wl[n * 64 + ch * 8]) = lo;
}

// ---------------- Kernel 1: tensor-core QKV projection ----------------
#define XA_H 0
#define XA_L 8192
#define WW_H 16384
#define WW_L 40960
#define PROJ_SMEM 65536

extern __shared__ char psm[];

__global__ __launch_bounds__(256, 2) void proj_kernel(const float* __restrict__ x)
{
    const int tid = threadIdx.x;
    const int wid = tid >> 5, lane = tid & 31;
    const int g = lane >> 2, tq = lane & 3;
    const int rows_base = blockIdx.x * 64;
    const uint32_t smb = smem_u32(psm);

    // ---- W tiles via cp.async (coalesced, L2-resident) ----
#pragma unroll
    for (int it = 0; it < 6; it++) {
        const int id = tid + it * 256;            // 0..1535
        const int n = id >> 3, ch = id & 7;
        const uint32_t off = n * 128 + ((ch ^ (n & 7)) << 4);
        CP_ASYNC16(smb + WW_H + off, g_wh + n * 64 + ch * 8);
        CP_ASYNC16(smb + WW_L + off, g_wl + n * 64 + ch * 8);
    }
    CP_COMMIT();

    // ---- x tile: fp32 -> fp16 hi/lo (through regs) ----
#pragma unroll
    for (int it = 0; it < 2; it++) {
        const int id = tid + it * 256;            // 0..511
        const int r = id >> 3, ch = id & 7;
        const float4* xp = reinterpret_cast<const float4*>(
            x + ((size_t)(rows_base + r)) * 64 + ch * 8);
        const float4 f0 = xp[0], f1 = xp[1];
        uint4 hi, lo;
        __half2 a, bq;
        a = __floats2half2_rn(f0.x, f0.y); hi.x = h2u(a);
        bq = __floats2half2_rn(f0.x - __half2float(__low2half(a)), f0.y - __half2float(__high2half(a))); lo.x = h2u(bq);
        a = __floats2half2_rn(f0.z, f0.w); hi.y = h2u(a);
        bq = __floats2half2_rn(f0.z - __half2float(__low2half(a)), f0.w - __half2float(__high2half(a))); lo.y = h2u(bq);
        a = __floats2half2_rn(f1.x, f1.y); hi.z = h2u(a);
        bq = __floats2half2_rn(f1.x - __half2float(__low2half(a)), f1.y - __half2float(__high2half(a))); lo.z = h2u(bq);
        a = __floats2half2_rn(f1.z, f1.w); hi.w = h2u(a);
        bq = __floats2half2_rn(f1.z - __half2float(__low2half(a)), f1.w - __half2float(__high2half(a))); lo.w = h2u(bq);
        const uint32_t off = r * 128 + ((ch ^ (r & 7)) << 4);
        *reinterpret_cast<uint4*>(psm + XA_H + off) = hi;
        *reinterpret_cast<uint4*>(psm + XA_L + off) = lo;
    }
    CP_WAIT(0);
    __syncthreads();

    const uint32_t* sAh = (const uint32_t*)(psm + XA_H);
    const uint32_t* sAl = (const uint32_t*)(psm + XA_L);
    const uint32_t* sWh = (const uint32_t*)(psm + WW_H);
    const uint32_t* sWl = (const uint32_t*)(psm + WW_L);

    uint32_t ah[16], al[16];
    {
        const int rb  = ((wid & 3) * 16 + g) * 32 + tq;
        const int rb8 = rb + 256;
#pragma unroll
        for (int kc = 0; kc < 4; kc++) {
            const int e0 = ((2 * kc) ^ g) << 2;
            const int e1 = ((2 * kc + 1) ^ g) << 2;
            ah[4*kc+0] = sAh[rb + e0];  ah[4*kc+1] = sAh[rb8 + e0];
            ah[4*kc+2] = sAh[rb + e1];  ah[4*kc+3] = sAh[rb8 + e1];
            al[4*kc+0] = sAl[rb + e0];  al[4*kc+1] = sAl[rb8 + e0];
            al[4*kc+2] = sAl[rb + e1];  al[4*kc+3] = sAl[rb8 + e1];
        }
    }

    const int nh = wid >> 2;                      // n-half: 0 or 1
    float D[12][4];
#pragma unroll
    for (int j = 0; j < 12; j++) { D[j][0]=0.f; D[j][1]=0.f; D[j][2]=0.f; D[j][3]=0.f; }

#pragma unroll
    for (int jj = 0; jj < 12; jj++) {
        const int jg = nh * 12 + jj;
        const int rbase = (8 * jg + g) * 32 + tq;
#pragma unroll
        for (int kc = 0; kc < 4; kc++) {
            const int e0 = ((2 * kc) ^ g) << 2;
            const int e1 = ((2 * kc + 1) ^ g) << 2;
            const uint32_t bh0 = sWh[rbase + e0], bh1 = sWh[rbase + e1];
            const uint32_t bl0 = sWl[rbase + e0], bl1 = sWl[rbase + e1];
            MMA16816(D[jj][0],D[jj][1],D[jj][2],D[jj][3], ah[4*kc],ah[4*kc+1],ah[4*kc+2],ah[4*kc+3], bh0,bh1);
            MMA16816(D[jj][0],D[jj][1],D[jj][2],D[jj][3], al[4*kc],al[4*kc+1],al[4*kc+2],al[4*kc+3], bh0,bh1);
            MMA16816(D[jj][0],D[jj][1],D[jj][2],D[jj][3], ah[4*kc],ah[4*kc+1],ah[4*kc+2],ah[4*kc+3], bl0,bl1);
        }
    }

    // ---- epilogue ----
    const int rg  = rows_base + (wid & 3) * 16 + g;
    const int rg8 = rg + 8;
    const int b = rg >> 12, t0 = rg & (T_ - 1), t8 = t0 + 8;

#pragma unroll
    for (int jj = 0; jj < 12; jj++) {
        const int j = nh * 12 + jj;
        const int h = 8 * (j & 7) + 2 * tq;
        float v0 = D[jj][0], v1 = D[jj][1], v2 = D[jj][2], v3 = D[jj][3];
        if (j < 8) { v0 *= QSCALE; v1 *= QSCALE; v2 *= QSCALE; v3 *= QSCALE; }  // Q * C**0.5 * log2(e)
        const __half2 hA = __floats2half2_rn(v0, v1);
        const __half2 hB = __floats2half2_rn(v2, v3);
        const __half2 lA = __floats2half2_rn(v0 - __half2float(__low2half(hA)),
                                             v1 - __half2float(__high2half(hA)));
        const __half2 lB = __floats2half2_rn(v2 - __half2float(__low2half(hB)),
                                             v3 - __half2float(__high2half(hB)));
        if (j < 8) {
            *(uint32_t*)&g_qh[(size_t)rg  * 64 + h] = h2u(hA);
            *(uint32_t*)&g_qh[(size_t)rg8 * 64 + h] = h2u(hB);
            *(uint32_t*)&g_ql[(size_t)rg  * 64 + h] = h2u(lA);
            *(uint32_t*)&g_ql[(size_t)rg8 * 64 + h] = h2u(lB);
        } else if (j < 16) {
            *(uint32_t*)&g_kh[(size_t)rg  * 64 + h] = h2u(hA);
            *(uint32_t*)&g_kh[(size_t)rg8 * 64 + h] = h2u(hB);
            *(uint32_t*)&g_kl[(size_t)rg  * 64 + h] = h2u(lA);
            *(uint32_t*)&g_kl[(size_t)rg8 * 64 + h] = h2u(lB);
        } else {
            const size_t r0 = ((size_t)b * 64 + h) * T_;
            const size_t r1 = ((size_t)b * 64 + h + 1) * T_;
            g_vh[r0 + t0] = __low2half(hA);  g_vh[r1 + t0] = __high2half(hA);
            g_vh[r0 + t8] = __low2half(hB);  g_vh[r1 + t8] = __high2half(hB);
            g_vl[r0 + t0] = __low2half(lA);  g_vl[r1 + t0] = __high2half(lA);
            g_vl[r0 + t8] = __low2half(lB);  g_vl[r1 + t8] = __high2half(lB);
        }
    }
}

// ---------------- Kernel 2: FA2-style mma.sync flash attention (split-K partials)
// SMEM: 2 x 32KB K/V double buffer + 32KB Q (hi/lo) = 96KB/CTA, 2 CTAs/SM.
#define ABYTES 8192
#define BUFBYTES (4 * ABYTES)
#define QH_OFF 65536
#define QL_OFF 81920
#define SMEM_BYTES 98304

extern __shared__ char dsm[];

__device__ __forceinline__ void copy_tile(int b, int k0, int buf, int tid, uint32_t smb)
{
#pragma unroll
    for (int i = 0; i < 8; i++) {
        const int id = tid + i * 256;           // 0..2047
        const int arr = id >> 9;                // 0..3 (uniform per i-range)
        const int r = (id >> 3) & 63;
        const int ch = id & 7;
        const uint32_t dst = smb + buf * BUFBYTES + arr * ABYTES + r * 128 + ((ch ^ (r & 7)) << 4);
        const __half* src;
        if (arr == 0)      src = g_kh + ((size_t)(b * T_ + k0 + r)) * 64 + ch * 8;
        else if (arr == 1) src = g_kl + ((size_t)(b * T_ + k0 + r)) * 64 + ch * 8;
        else if (arr == 2) src = g_vh + ((size_t)(b * 64 + r)) * T_ + k0 + ch * 8;
        else               src = g_vl + ((size_t)(b * 64 + r)) * T_ + k0 + ch * 8;
        CP_ASYNC16(dst, src);
    }
}

__device__ __forceinline__ void copy_q(int b, int q0, int tid, uint32_t smb)
{
#pragma unroll
    for (int i = 0; i < 8; i++) {
        const int id = tid + i * 256;           // 0..2047
        const int arr = id >> 10;               // 0=qh, 1=ql
        const int r = (id >> 3) & 127;
        const int ch = id & 7;
        const uint32_t dst = smb + QH_OFF + arr * 16384 + r * 128 + ((ch ^ (r & 7)) << 4);
        const __half* src = (arr == 0 ? g_qh : g_ql) + ((size_t)(b * T_ + q0 + r)) * 64 + ch * 8;
        CP_ASYNC16(dst, src);
    }
}

__global__ __launch_bounds__(256, 2) void attn_kernel()
{
    const int b = blockIdx.y;
    // heavy-first (t, c) mapping: q-tile t has t/8+1 chunks; sum = 80
    int u = blockIdx.x, t = 0, c = 0;
#pragma unroll 1
    for (int tt = 31; tt >= 0; tt--) { int n = tt / 8 + 1; if (u < n) { t = tt; c = u; break; } u -= n; }
    const int q0 = t * BM, k0c = c * KC;
    const int kend = min(k0c + KC, (t + 1) * BM);
    const int nT = (kend - k0c) / KN;

    const int tid = threadIdx.x, wid = tid >> 5, lane = tid & 31;
    const int g = lane >> 2, tq = lane & 3;
    const int qi0 = q0 + wid * 16;
    const int rg = qi0 + g, rg8 = rg + 8;
    const uint32_t smb = smem_u32(dsm);

    // ldmatrix lane decomposition
    const int lr = lane & 7, q2 = lane >> 3;
    const uint32_t kv_row = (uint32_t)(((q2 >> 1) * 8 + lr) * 128);   // K/V: m-pair row offset
    const int eKV = q2 & 1;                                           // K/V: which k-chunk
    const uint32_t q_row = (uint32_t)((wid * 16 + (q2 & 1) * 8 + lr) * 128);  // Q rows
    const int eQ = q2 >> 1;

    float O[8][4];
#pragma unroll
    for (int j = 0; j < 8; j++) { O[j][0]=0.f; O[j][1]=0.f; O[j][2]=0.f; O[j][3]=0.f; }
    float Ol[4] = {0.f, 0.f, 0.f, 0.f};          // ones-column accumulator: l
    float m0 = -1e30f, m1 = -1e30f;

    copy_q(b, q0, tid, smb);
    copy_tile(b, k0c, 0, tid, smb);
    CP_COMMIT();

    for (int n = 0; n < nT; n++) {
        const int k0 = k0c + n * KN;
        const int buf = n & 1;
        __syncthreads();                          // prev compute done before overwrite
        if (n + 1 < nT) { copy_tile(b, k0 + KN, (n + 1) & 1, tid, smb); CP_COMMIT(); CP_WAIT(1); }
        else            { CP_WAIT(0); }
        __syncthreads();                          // tile n (and Q) visible to all

        const uint32_t kh_base = smb + buf * BUFBYTES + kv_row;
        const uint32_t vh_base = kh_base + 2 * ABYTES;

        // ---- S = Q·K^T (3-term hi/lo), ldmatrix fragment loads; scores in log2 units ----
        float SD[8][4];
#pragma unroll
        for (int j = 0; j < 8; j++) { SD[j][0]=0.f; SD[j][1]=0.f; SD[j][2]=0.f; SD[j][3]=0.f; }
#pragma unroll
        for (int kc = 0; kc < 4; kc++) {
            const uint32_t chQ = (uint32_t)(((2 * kc + eQ) ^ lr) << 4);
            uint32_t a0, a1, a2, a3, c0r, c1r, c2r, c3r;
            LDSM4(a0, a1, a2, a3, smb + QH_OFF + q_row + chQ);
            LDSM4(c0r, c1r, c2r, c3r, smb + QL_OFF + q_row + chQ);
            const uint32_t chK = (uint32_t)(((2 * kc + eKV) ^ lr) << 4);
#pragma unroll
            for (int j0 = 0; j0 < 8; j0 += 2) {
                uint32_t bh0, bh1, bh2, bh3, bl0, bl1, bl2, bl3;
                LDSM4(bh0, bh1, bh2, bh3, kh_base + chK + j0 * 1024);
                LDSM4(bl0, bl1, bl2, bl3, kh_base + ABYTES + chK + j0 * 1024);
                MMA16816(SD[j0][0],SD[j0][1],SD[j0][2],SD[j0][3], a0,a1,a2,a3, bh0,bh1);
                MMA16816(SD[j0][0],SD[j0][1],SD[j0][2],SD[j0][3], c0r,c1r,c2r,c3r, bh0,bh1);
                MMA16816(SD[j0][0],SD[j0][1],SD[j0][2],SD[j0][3], a0,a1,a2,a3, bl0,bl1);
                MMA16816(SD[j0+1][0],SD[j0+1][1],SD[j0+1][2],SD[j0+1][3], a0,a1,a2,a3, bh2,bh3);
                MMA16816(SD[j0+1][0],SD[j0+1][1],SD[j0+1][2],SD[j0+1][3], c0r,c1r,c2r,c3r, bh2,bh3);
                MMA16816(SD[j0+1][0],SD[j0+1][1],SD[j0+1][2],SD[j0+1][3], a0,a1,a2,a3, bl2,bl3);
            }
        }

        // ---- causal mask (warp-uniform predicate) ----
        if (k0 + KN - 1 > qi0) {
#pragma unroll
            for (int j = 0; j < 8; j++) {
                const int col = k0 + 8 * j + 2 * tq;
                if (col     > rg)  SD[j][0] = -1e30f;
                if (col + 1 > rg)  SD[j][1] = -1e30f;
                if (col     > rg8) SD[j][2] = -1e30f;
                if (col + 1 > rg8) SD[j][3] = -1e30f;
            }
        }

        // ---- online softmax (log2 domain) ----
        float bm0 = -1e30f, bm1 = -1e30f;
#pragma unroll
        for (int j = 0; j < 8; j++) {
            bm0 = fmaxf(bm0, fmaxf(SD[j][0], SD[j][1]));
            bm1 = fmaxf(bm1, fmaxf(SD[j][2], SD[j][3]));
        }
        bm0 = fmaxf(bm0, __shfl_xor_sync(0xFFFFFFFFu, bm0, 1));
        bm0 = fmaxf(bm0, __shfl_xor_sync(0xFFFFFFFFu, bm0, 2));
        bm1 = fmaxf(bm1, __shfl_xor_sync(0xFFFFFFFFu, bm1, 1));
        bm1 = fmaxf(bm1, __shfl_xor_sync(0xFFFFFFFFu, bm1, 2));
        const float mn0 = fmaxf(m0, bm0), mn1 = fmaxf(m1, bm1);
        const float c0 = ex2f(m0 - mn0), c1 = ex2f(m1 - mn1);
        m0 = mn0; m1 = mn1;

#pragma unroll
        for (int j = 0; j < 8; j++) {
            O[j][0] *= c0; O[j][1] *= c0; O[j][2] *= c1; O[j][3] *= c1;
        }
        Ol[0] *= c0; Ol[1] *= c0; Ol[2] *= c1; Ol[3] *= c1;

        // ---- O += P·V  (p = ex2.f16x2(s - m); l via ones-column MMA) ----
#pragma unroll
        for (int kc = 0; kc < 4; kc++) {
            const uint32_t pa0 = ex2h2(h2u(__floats2half2_rn(SD[2*kc][0]   - mn0, SD[2*kc][1]   - mn0)));
            const uint32_t pa1 = ex2h2(h2u(__floats2half2_rn(SD[2*kc][2]   - mn1, SD[2*kc][3]   - mn1)));
            const uint32_t pa2 = ex2h2(h2u(__floats2half2_rn(SD[2*kc+1][0] - mn0, SD[2*kc+1][1] - mn0)));
            const uint32_t pa3 = ex2h2(h2u(__floats2half2_rn(SD[2*kc+1][2] - mn1, SD[2*kc+1][3] - mn1)));
            MMA16816(Ol[0],Ol[1],Ol[2],Ol[3], pa0,pa1,pa2,pa3, ONES16,ONES16);
            const uint32_t chV = (uint32_t)(((2 * kc + eKV) ^ lr) << 4);
#pragma unroll
            for (int j0 = 0; j0 < 8; j0 += 2) {
                uint32_t vh0, vh1, vh2, vh3, vl0, vl1, vl2, vl3;
                LDSM4(vh0, vh1, vh2, vh3, vh_base + chV + j0 * 1024);
                LDSM4(vl0, vl1, vl2, vl3, vh_base + ABYTES + chV + j0 * 1024);
                MMA16816(O[j0][0],O[j0][1],O[j0][2],O[j0][3], pa0,pa1,pa2,pa3, vh0,vh1);
                MMA16816(O[j0][0],O[j0][1],O[j0][2],O[j0][3], pa0,pa1,pa2,pa3, vl0,vl1);
                MMA16816(O[j0+1][0],O[j0+1][1],O[j0+1][2],O[j0+1][3], pa0,pa1,pa2,pa3, vh2,vh3);
                MMA16816(O[j0+1][0],O[j0+1][1],O[j0+1][2],O[j0+1][3], pa0,pa1,pa2,pa3, vl2,vl3);
            }
        }
    }

    // ---- write partials (m in log2 units; l from ones-column, all lanes hold it) ----
    const size_t p0 = ((size_t)(b * T_ + rg)) * NCMAX + c;
    const size_t p1 = ((size_t)(b * T_ + rg8)) * NCMAX + c;
    if (tq == 0) {
        g_pm[p0] = m0; g_pl[p0] = Ol[0];
        g_pm[p1] = m1; g_pl[p1] = Ol[2];
    }
#pragma unroll
    for (int j = 0; j < 8; j++) {
        float2 a; a.x = O[j][0]; a.y = O[j][1];
        float2 d; d.x = O[j][2]; d.y = O[j][3];
        *(float2*)&g_po[p0 * 64 + 8 * j + 2 * tq] = a;
        *(float2*)&g_po[p1 * 64 + 8 * j + 2 * tq] = d;
    }
}

// ---------------- Kernel 3: merge split-K partials (parallel: thread = (row, float4))
__global__ __launch_bounds__(256) void attn_reduce_kernel(float* __restrict__ out)
{
    const int gid2 = blockIdx.x * 256 + threadIdx.x;   // 0 .. B*T*16
    const int row = gid2 >> 4, part = gid2 & 15;
    const int qi = row & (T_ - 1);
    const int nc = (qi >> 7) / 8 + 1;
    const size_t pbase = (size_t)row * NCMAX;

    float mv[NCMAX];
#pragma unroll
    for (int cc = 0; cc < NCMAX; cc++) mv[cc] = (cc < nc) ? g_pm[pbase + cc] : -1e30f;
    float m = -1e30f;
#pragma unroll
    for (int cc = 0; cc < NCMAX; cc++) m = fmaxf(m, mv[cc]);

    float l = 0.f;
    float ox = 0.f, oy = 0.f, oz = 0.f, ow = 0.f;
#pragma unroll
    for (int cc = 0; cc < NCMAX; cc++) {
        if (cc < nc) {
            const float w = ex2f(mv[cc] - m);      // log2-domain partials
            l = fmaf(g_pl[pbase + cc], w, l);
            const float4 v = *reinterpret_cast<const float4*>(
                &g_po[(pbase + cc) * HS_ + part * 4]);
            ox = fmaf(w, v.x, ox); oy = fmaf(w, v.y, oy);
            oz = fmaf(w, v.z, oz); ow = fmaf(w, v.w, ow);
        }
    }
    const float inv = 1.0f / l;
    float4 r;
    r.x = ox * inv; r.y = oy * inv; r.z = oz * inv; r.w = ow * inv;
    *reinterpret_cast<float4*>(&out[(size_t)row * HS_ + part * 4]) = r;
}

// ---------------------------------------------------------------------------
extern "C" void kernel_launch(void* const* d_in, const int* in_sizes, int n_in,
                              void* d_out, int out_size)
{
    const float* x  = (const float*)d_in[0];
    const float* Wq = (const float*)d_in[1];
    const float* Wk = (const float*)d_in[2];
    const float* Wv = (const float*)d_in[3];
    float* out = (float*)d_out;

    cudaFuncSetAttribute(proj_kernel, cudaFuncAttributeMaxDynamicSharedMemorySize, PROJ_SMEM);
    cudaFuncSetAttribute(attn_kernel, cudaFuncAttributeMaxDynamicSharedMemorySize, SMEM_BYTES);

    wconv_kernel<<<6, 256>>>(Wq, Wk, Wv);
    proj_kernel<<<(B_ * T_) / 64, 256, PROJ_SMEM>>>(x);

    dim3 ag(80, B_);
    attn_kernel<<<ag, 256, SMEM_BYTES>>>();

    attn_reduce_kernel<<<(B_ * T_ * 16) / 256, 256>>>(out);
}

// round 12
// speedup vs baseline: 9.5092x; 1.1443x over previous
#include <cuda_runtime.h>
#include <cuda_fp16.h>
#include <cstdint>

#define B_ 4
#define T_ 4096
#define HS_ 64
#define BM 128
#define KN 64
#define KC 1024
#define NCMAX 4

// Device scratch (no cudaMalloc allowed). 16B-aligned for vector/cp.async access.
__device__ __align__(16) __half g_qh[B_*T_*HS_], g_ql[B_*T_*HS_];
__device__ __align__(16) __half g_kh[B_*T_*HS_], g_kl[B_*T_*HS_];
__device__ __align__(16) __half g_vh[B_*HS_*T_];                    // V^T: [b][h][t] (hi only)
__device__ __align__(16) __half g_wh[192*64], g_wl[192*64];         // stacked [Wq;Wk;Wv]^T
__device__ float g_pm[B_*T_*NCMAX], g_pl[B_*T_*NCMAX];              // m in log2 units
__device__ float g_po[(size_t)B_*T_*NCMAX*HS_];

// ---------------- PTX helpers (family-agnostic: sm_80+) ----------------
__device__ __forceinline__ uint32_t smem_u32(const void* p) {
    uint32_t a;
    asm("{ .reg .u64 t; cvta.to.shared.u64 t, %1; cvt.u32.u64 %0, t; }" : "=r"(a) : "l"(p));
    return a;
}
#define CP_ASYNC16(dst, src) \
    asm volatile("cp.async.cg.shared.global [%0], [%1], 16;" :: "r"(dst), "l"(src))
#define CP_COMMIT() asm volatile("cp.async.commit_group;" ::: "memory")
#define CP_WAIT(n)  asm volatile("cp.async.wait_group %0;" :: "n"(n) : "memory")

// D(16x8,f32) += A(16x16,f16) * B(16x8,f16)   row.col
#define MMA16816(D0,D1,D2,D3, A0,A1,A2,A3, B0,B1) \
    asm volatile("mma.sync.aligned.m16n8k16.row.col.f32.f16.f16.f32 " \
        "{%0,%1,%2,%3}, {%4,%5,%6,%7}, {%8,%9}, {%0,%1,%2,%3};" \
        : "+f"(D0), "+f"(D1), "+f"(D2), "+f"(D3) \
        : "r"(A0), "r"(A1), "r"(A2), "r"(A3), "r"(B0), "r"(B1))

#define LDSM4(R0,R1,R2,R3, ADDR) \
    asm volatile("ldmatrix.sync.aligned.m8n8.x4.shared.b16 {%0,%1,%2,%3}, [%4];" \
        : "=r"(R0), "=r"(R1), "=r"(R2), "=r"(R3) : "r"(ADDR))

__device__ __forceinline__ uint32_t h2u(__half2 h) { return *(uint32_t*)&h; }
__device__ __forceinline__ float ex2f(float x) {
    float r; asm("ex2.approx.f32 %0, %1;" : "=f"(r) : "f"(x)); return r;
}
__device__ __forceinline__ uint32_t ex2h2(uint32_t x) {
    uint32_t r; asm("ex2.approx.f16x2 %0, %1;" : "=r"(r) : "r"(x)); return r;
}
#define ONES16 0x3C003C00u   // half2(1.0, 1.0)

// Q scale: 8 (the reference's C**0.5) * log2(e) -> scores arrive in log2 units
#define QSCALE 11.5415603271117f

// ---------------- Kernel 0: W -> fp16 hi/lo, stacked [n=mat*64+h][k=d] ----------------
__global__ __launch_bounds__(256) void wconv_kernel(
    const float* __restrict__ Wq, const float* __restrict__ Wk, const float* __restrict__ Wv)
{
    const int id = blockIdx.x * 256 + threadIdx.x;    // 0..1535
    const int n = id >> 3, ch = id & 7;
    const int m = n >> 6, h = n & 63;
    const float* W = m == 0 ? Wq : (m == 1 ? Wk : Wv);
    float f[8];
#pragma unroll
    for (int dd = 0; dd < 8; dd++) f[dd] = W[(ch * 8 + dd) * 64 + h];
    uint4 hi, lo;
    uint32_t* hp = &hi.x;
    uint32_t* lp = &lo.x;
#pragma unroll
    for (int p = 0; p < 4; p++) {
        __half2 a = __floats2half2_rn(f[2*p], f[2*p+1]);
        hp[p] = h2u(a);
        __half2 bq = __floats2half2_rn(f[2*p]   - __half2float(__low2half(a)),
                                       f[2*p+1] - __half2float(__high2half(a)));
        lp[p] = h2u(bq);
    }
    *reinterpret_cast<uint4*>(&g_wh[n * 64 + ch * 8]) = hi;
    *reinterpret_cast<uint4*>(&g_wl[n * 64 + ch * 8]) = lo;
}

// ---------------- Kernel 1: tensor-core QKV projection ----------------
#define XA_H 0
#define XA_L 8192
#define WW_H 16384
#define WW_L 40960
#define PROJ_SMEM 65536

extern __shared__ char psm[];

__global__ __launch_bounds__(256, 2) void proj_kernel(const float* __restrict__ x)
{
    const int tid = threadIdx.x;
    const int wid = tid >> 5, lane = tid & 31;
    const int g = lane >> 2, tq = lane & 3;
    const int rows_base = blockIdx.x * 64;
    const uint32_t smb = smem_u32(psm);

    // ---- W tiles via cp.async (coalesced, L2-resident) ----
#pragma unroll
    for (int it = 0; it < 6; it++) {
        const int id = tid + it * 256;            // 0..1535
        const int n = id >> 3, ch = id & 7;
        const uint32_t off = n * 128 + ((ch ^ (n & 7)) << 4);
        CP_ASYNC16(smb + WW_H + off, g_wh + n * 64 + ch * 8);
        CP_ASYNC16(smb + WW_L + off, g_wl + n * 64 + ch * 8);
    }
    CP_COMMIT();

    // ---- x tile: fp32 -> fp16 hi/lo (through regs) ----
#pragma unroll
    for (int it = 0; it < 2; it++) {
        const int id = tid + it * 256;            // 0..511
        const int r = id >> 3, ch = id & 7;
        const float4* xp = reinterpret_cast<const float4*>(
            x + ((size_t)(rows_base + r)) * 64 + ch * 8);
        const float4 f0 = xp[0], f1 = xp[1];
        uint4 hi, lo;
        __half2 a, bq;
        a = __floats2half2_rn(f0.x, f0.y); hi.x = h2u(a);
        bq = __floats2half2_rn(f0.x - __half2float(__low2half(a)), f0.y - __half2float(__high2half(a))); lo.x = h2u(bq);
        a = __floats2half2_rn(f0.z, f0.w); hi.y = h2u(a);
        bq = __floats2half2_rn(f0.z - __half2float(__low2half(a)), f0.w - __half2float(__high2half(a))); lo.y = h2u(bq);
        a = __floats2half2_rn(f1.x, f1.y); hi.z = h2u(a);
        bq = __floats2half2_rn(f1.x - __half2float(__low2half(a)), f1.y - __half2float(__high2half(a))); lo.z = h2u(bq);
        a = __floats2half2_rn(f1.z, f1.w); hi.w = h2u(a);
        bq = __floats2half2_rn(f1.z - __half2float(__low2half(a)), f1.w - __half2float(__high2half(a))); lo.w = h2u(bq);
        const uint32_t off = r * 128 + ((ch ^ (r & 7)) << 4);
        *reinterpret_cast<uint4*>(psm + XA_H + off) = hi;
        *reinterpret_cast<uint4*>(psm + XA_L + off) = lo;
    }
    CP_WAIT(0);
    __syncthreads();

    const uint32_t* sAh = (const uint32_t*)(psm + XA_H);
    const uint32_t* sAl = (const uint32_t*)(psm + XA_L);
    const uint32_t* sWh = (const uint32_t*)(psm + WW_H);
    const uint32_t* sWl = (const uint32_t*)(psm + WW_L);

    uint32_t ah[16], al[16];
    {
        const int rb  = ((wid & 3) * 16 + g) * 32 + tq;
        const int rb8 = rb + 256;
#pragma unroll
        for (int kc = 0; kc < 4; kc++) {
            const int e0 = ((2 * kc) ^ g) << 2;
            const int e1 = ((2 * kc + 1) ^ g) << 2;
            ah[4*kc+0] = sAh[rb + e0];  ah[4*kc+1] = sAh[rb8 + e0];
            ah[4*kc+2] = sAh[rb + e1];  ah[4*kc+3] = sAh[rb8 + e1];
            al[4*kc+0] = sAl[rb + e0];  al[4*kc+1] = sAl[rb8 + e0];
            al[4*kc+2] = sAl[rb + e1];  al[4*kc+3] = sAl[rb8 + e1];
        }
    }

    const int nh = wid >> 2;                      // n-half: 0 or 1
    float D[12][4];
#pragma unroll
    for (int j = 0; j < 12; j++) { D[j][0]=0.f; D[j][1]=0.f; D[j][2]=0.f; D[j][3]=0.f; }

#pragma unroll
    for (int jj = 0; jj < 12; jj++) {
        const int jg = nh * 12 + jj;
        const int rbase = (8 * jg + g) * 32 + tq;
#pragma unroll
        for (int kc = 0; kc < 4; kc++) {
            const int e0 = ((2 * kc) ^ g) << 2;
            const int e1 = ((2 * kc + 1) ^ g) << 2;
            const uint32_t bh0 = sWh[rbase + e0], bh1 = sWh[rbase + e1];
            const uint32_t bl0 = sWl[rbase + e0], bl1 = sWl[rbase + e1];
            MMA16816(D[jj][0],D[jj][1],D[jj][2],D[jj][3], ah[4*kc],ah[4*kc+1],ah[4*kc+2],ah[4*kc+3], bh0,bh1);
            MMA16816(D[jj][0],D[jj][1],D[jj][2],D[jj][3], al[4*kc],al[4*kc+1],al[4*kc+2],al[4*kc+3], bh0,bh1);
            MMA16816(D[jj][0],D[jj][1],D[jj][2],D[jj][3], ah[4*kc],ah[4*kc+1],ah[4*kc+2],ah[4*kc+3], bl0,bl1);
        }
    }

    // ---- epilogue ----
    const int rg  = rows_base + (wid & 3) * 16 + g;
    const int rg8 = rg + 8;
    const int b = rg >> 12, t0 = rg & (T_ - 1), t8 = t0 + 8;

#pragma unroll
    for (int jj = 0; jj < 12; jj++) {
        const int j = nh * 12 + jj;
        const int h = 8 * (j & 7) + 2 * tq;
        float v0 = D[jj][0], v1 = D[jj][1], v2 = D[jj][2], v3 = D[jj][3];
        if (j < 8) { v0 *= QSCALE; v1 *= QSCALE; v2 *= QSCALE; v3 *= QSCALE; }  // Q * C**0.5 * log2(e)
        const __half2 hA = __floats2half2_rn(v0, v1);
        const __half2 hB = __floats2half2_rn(v2, v3);
        const __half2 lA = __floats2half2_rn(v0 - __half2float(__low2half(hA)),
                                             v1 - __half2float(__high2half(hA)));
        const __half2 lB = __floats2half2_rn(v2 - __half2float(__low2half(hB)),
                                             v3 - __half2float(__high2half(hB)));
        if (j < 8) {
            *(uint32_t*)&g_qh[(size_t)rg  * 64 + h] = h2u(hA);
            *(uint32_t*)&g_qh[(size_t)rg8 * 64 + h] = h2u(hB);
            *(uint32_t*)&g_ql[(size_t)rg  * 64 + h] = h2u(lA);
            *(uint32_t*)&g_ql[(size_t)rg8 * 64 + h] = h2u(lB);
        } else if (j < 16) {
            *(uint32_t*)&g_kh[(size_t)rg  * 64 + h] = h2u(hA);
            *(uint32_t*)&g_kh[(size_t)rg8 * 64 + h] = h2u(hB);
            *(uint32_t*)&g_kl[(size_t)rg  * 64 + h] = h2u(lA);
            *(uint32_t*)&g_kl[(size_t)rg8 * 64 + h] = h2u(lB);
        } else {
            const size_t r0 = ((size_t)b * 64 + h) * T_;
            const size_t r1 = ((size_t)b * 64 + h + 1) * T_;
            g_vh[r0 + t0] = __low2half(hA);  g_vh[r1 + t0] = __high2half(hA);
            g_vh[r0 + t8] = __low2half(hB);  g_vh[r1 + t8] = __high2half(hB);
        }
    }
}

// ---------------- Kernel 2: FA2-style mma.sync flash attention (split-K partials)
// SMEM: 2 x 24KB K/V double buffer (Kh,Kl,Vh) + 32KB Q (hi/lo) = 80KB/CTA, 2 CTAs/SM.
#define ABYTES 8192
#define BUFBYTES (3 * ABYTES)
#define QH_OFF 49152
#define QL_OFF 65536
#define SMEM_BYTES 81920

extern __shared__ char dsm[];

__device__ __forceinline__ void copy_tile(int b, int k0, int buf, int tid, uint32_t smb)
{
#pragma unroll
    for (int i = 0; i < 6; i++) {
        const int id = tid + i * 256;           // 0..1535
        const int arr = id >> 9;                // 0=Kh 1=Kl 2=Vh (uniform per i-range)
        const int r = (id >> 3) & 63;
        const int ch = id & 7;
        const uint32_t dst = smb + buf * BUFBYTES + arr * ABYTES + r * 128 + ((ch ^ (r & 7)) << 4);
        const __half* src;
        if (arr == 0)      src = g_kh + ((size_t)(b * T_ + k0 + r)) * 64 + ch * 8;
        else if (arr == 1) src = g_kl + ((size_t)(b * T_ + k0 + r)) * 64 + ch * 8;
        else               src = g_vh + ((size_t)(b * 64 + r)) * T_ + k0 + ch * 8;
        CP_ASYNC16(dst, src);
    }
}

__device__ __forceinline__ void copy_q(int b, int q0, int tid, uint32_t smb)
{
#pragma unroll
    for (int i = 0; i < 8; i++) {
        const int id = tid + i * 256;           // 0..2047
        const int arr = id >> 10;               // 0=qh, 1=ql
        const int r = (id >> 3) & 127;
        const int ch = id & 7;
        const uint32_t dst = smb + QH_OFF + arr * 16384 + r * 128 + ((ch ^ (r & 7)) << 4);
        const __half* src = (arr == 0 ? g_qh : g_ql) + ((size_t)(b * T_ + q0 + r)) * 64 + ch * 8;
        CP_ASYNC16(dst, src);
    }
}

__global__ __launch_bounds__(256, 2) void attn_kernel()
{
    const int b = blockIdx.y;
    // heavy-first (t, c) mapping: q-tile t has t/8+1 chunks; sum = 80
    int u = blockIdx.x, t = 0, c = 0;
#pragma unroll 1
    for (int tt = 31; tt >= 0; tt--) { int n = tt / 8 + 1; if (u < n) { t = tt; c = u; break; } u -= n; }
    const int q0 = t * BM, k0c = c * KC;
    const int kend = min(k0c + KC, (t + 1) * BM);
    const int nT = (kend - k0c) / KN;

    const int tid = threadIdx.x, wid = tid >> 5, lane = tid & 31;
    const int g = lane >> 2, tq = lane & 3;
    const int qi0 = q0 + wid * 16;
    const int rg = qi0 + g, rg8 = rg + 8;
    const uint32_t smb = smem_u32(dsm);

    // ldmatrix lane decomposition
    const int lr = lane & 7, q2 = lane >> 3;
    const uint32_t kv_row = (uint32_t)(((q2 >> 1) * 8 + lr) * 128);   // K/V: m-pair row offset
    const int eKV = q2 & 1;                                           // K/V: which k-chunk
    const uint32_t q_row = (uint32_t)((wid * 16 + (q2 & 1) * 8 + lr) * 128);  // Q rows
    const int eQ = q2 >> 1;

    float O[8][4];
#pragma unroll
    for (int j = 0; j < 8; j++) { O[j][0]=0.f; O[j][1]=0.f; O[j][2]=0.f; O[j][3]=0.f; }
    float Ol[4] = {0.f, 0.f, 0.f, 0.f};          // ones-column accumulator: l
    float m0 = -1e30f, m1 = -1e30f;

    copy_q(b, q0, tid, smb);
    copy_tile(b, k0c, 0, tid, smb);
    CP_COMMIT();
    CP_WAIT(0);
    __syncthreads();

    // ---- hoist Q-hi fragments (tile-invariant) into registers ----
    uint32_t qfh[16];
#pragma unroll
    for (int kc = 0; kc < 4; kc++) {
        const uint32_t chQ = (uint32_t)(((2 * kc + eQ) ^ lr) << 4);
        LDSM4(qfh[4*kc], qfh[4*kc+1], qfh[4*kc+2], qfh[4*kc+3], smb + QH_OFF + q_row + chQ);
    }

    for (int n = 0; n < nT; n++) {
        const int k0 = k0c + n * KN;
        const int buf = n & 1;
        __syncthreads();                          // prev compute done before overwrite
        if (n + 1 < nT) { copy_tile(b, k0 + KN, (n + 1) & 1, tid, smb); CP_COMMIT(); CP_WAIT(1); }
        else            { CP_WAIT(0); }
        __syncthreads();                          // tile n visible to all

        const uint32_t kh_base = smb + buf * BUFBYTES + kv_row;
        const uint32_t vh_base = kh_base + 2 * ABYTES;

        // ---- S = Q·K^T (3-term hi/lo), Q-hi from regs; scores in log2 units ----
        float SD[8][4];
#pragma unroll
        for (int j = 0; j < 8; j++) { SD[j][0]=0.f; SD[j][1]=0.f; SD[j][2]=0.f; SD[j][3]=0.f; }
#pragma unroll
        for (int kc = 0; kc < 4; kc++) {
            const uint32_t chQ = (uint32_t)(((2 * kc + eQ) ^ lr) << 4);
            uint32_t c0r, c1r, c2r, c3r;
            LDSM4(c0r, c1r, c2r, c3r, smb + QL_OFF + q_row + chQ);
            const uint32_t a0 = qfh[4*kc], a1 = qfh[4*kc+1], a2 = qfh[4*kc+2], a3 = qfh[4*kc+3];
            const uint32_t chK = (uint32_t)(((2 * kc + eKV) ^ lr) << 4);
#pragma unroll
            for (int j0 = 0; j0 < 8; j0 += 2) {
                uint32_t bh0, bh1, bh2, bh3, bl0, bl1, bl2, bl3;
                LDSM4(bh0, bh1, bh2, bh3, kh_base + chK + j0 * 1024);
                LDSM4(bl0, bl1, bl2, bl3, kh_base + ABYTES + chK + j0 * 1024);
                MMA16816(SD[j0][0],SD[j0][1],SD[j0][2],SD[j0][3], a0,a1,a2,a3, bh0,bh1);
                MMA16816(SD[j0][0],SD[j0][1],SD[j0][2],SD[j0][3], c0r,c1r,c2r,c3r, bh0,bh1);
                MMA16816(SD[j0][0],SD[j0][1],SD[j0][2],SD[j0][3], a0,a1,a2,a3, bl0,bl1);
                MMA16816(SD[j0+1][0],SD[j0+1][1],SD[j0+1][2],SD[j0+1][3], a0,a1,a2,a3, bh2,bh3);
                MMA16816(SD[j0+1][0],SD[j0+1][1],SD[j0+1][2],SD[j0+1][3], c0r,c1r,c2r,c3r, bh2,bh3);
                MMA16816(SD[j0+1][0],SD[j0+1][1],SD[j0+1][2],SD[j0+1][3], a0,a1,a2,a3, bl2,bl3);
            }
        }

        // ---- causal mask (warp-uniform predicate) ----
        if (k0 + KN - 1 > qi0) {
#pragma unroll
            for (int j = 0; j < 8; j++) {
                const int col = k0 + 8 * j + 2 * tq;
                if (col     > rg)  SD[j][0] = -1e30f;
                if (col + 1 > rg)  SD[j][1] = -1e30f;
                if (col     > rg8) SD[j][2] = -1e30f;
                if (col + 1 > rg8) SD[j][3] = -1e30f;
            }
        }

        // ---- online softmax (log2 domain) ----
        float bm0 = -1e30f, bm1 = -1e30f;
#pragma unroll
        for (int j = 0; j < 8; j++) {
            bm0 = fmaxf(bm0, fmaxf(SD[j][0], SD[j][1]));
            bm1 = fmaxf(bm1, fmaxf(SD[j][2], SD[j][3]));
        }
        bm0 = fmaxf(bm0, __shfl_xor_sync(0xFFFFFFFFu, bm0, 1));
        bm0 = fmaxf(bm0, __shfl_xor_sync(0xFFFFFFFFu, bm0, 2));
        bm1 = fmaxf(bm1, __shfl_xor_sync(0xFFFFFFFFu, bm1, 1));
        bm1 = fmaxf(bm1, __shfl_xor_sync(0xFFFFFFFFu, bm1, 2));
        const float mn0 = fmaxf(m0, bm0), mn1 = fmaxf(m1, bm1);
        const float c0 = ex2f(m0 - mn0), c1 = ex2f(m1 - mn1);
        m0 = mn0; m1 = mn1;

#pragma unroll
        for (int j = 0; j < 8; j++) {
            O[j][0] *= c0; O[j][1] *= c0; O[j][2] *= c1; O[j][3] *= c1;
        }
        Ol[0] *= c0; Ol[1] *= c0; Ol[2] *= c1; Ol[3] *= c1;

        // ---- O += P·V  (p = ex2.f16x2(s - m); l via ones-column MMA; V hi only) ----
#pragma unroll
        for (int kc = 0; kc < 4; kc++) {
            const uint32_t pa0 = ex2h2(h2u(__floats2half2_rn(SD[2*kc][0]   - mn0, SD[2*kc][1]   - mn0)));
            const uint32_t pa1 = ex2h2(h2u(__floats2half2_rn(SD[2*kc][2]   - mn1, SD[2*kc][3]   - mn1)));
            const uint32_t pa2 = ex2h2(h2u(__floats2half2_rn(SD[2*kc+1][0] - mn0, SD[2*kc+1][1] - mn0)));
            const uint32_t pa3 = ex2h2(h2u(__floats2half2_rn(SD[2*kc+1][2] - mn1, SD[2*kc+1][3] - mn1)));
            MMA16816(Ol[0],Ol[1],Ol[2],Ol[3], pa0,pa1,pa2,pa3, ONES16,ONES16);
            const uint32_t chV = (uint32_t)(((2 * kc + eKV) ^ lr) << 4);
#pragma unroll
            for (int j0 = 0; j0 < 8; j0 += 2) {
                uint32_t vh0, vh1, vh2, vh3;
                LDSM4(vh0, vh1, vh2, vh3, vh_base + chV + j0 * 1024);
                MMA16816(O[j0][0],O[j0][1],O[j0][2],O[j0][3], pa0,pa1,pa2,pa3, vh0,vh1);
                MMA16816(O[j0+1][0],O[j0+1][1],O[j0+1][2],O[j0+1][3], pa0,pa1,pa2,pa3, vh2,vh3);
            }
        }
    }

    // ---- write partials (m in log2 units; l from ones-column, all lanes hold it) ----
    const size_t p0 = ((size_t)(b * T_ + rg)) * NCMAX + c;
    const size_t p1 = ((size_t)(b * T_ + rg8)) * NCMAX + c;
    if (tq == 0) {
        g_pm[p0] = m0; g_pl[p0] = Ol[0];
        g_pm[p1] = m1; g_pl[p1] = Ol[2];
    }
#pragma unroll
    for (int j = 0; j < 8; j++) {
        float2 a; a.x = O[j][0]; a.y = O[j][1];
        float2 d; d.x = O[j][2]; d.y = O[j][3];
        *(float2*)&g_po[p0 * 64 + 8 * j + 2 * tq] = a;
        *(float2*)&g_po[p1 * 64 + 8 * j + 2 * tq] = d;
    }
}

// ---------------- Kernel 3: merge split-K partials (parallel: thread = (row, float4))
__global__ __launch_bounds__(256) void attn_reduce_kernel(float* __restrict__ out)
{
    const int gid2 = blockIdx.x * 256 + threadIdx.x;   // 0 .. B*T*16
    const int row = gid2 >> 4, part = gid2 & 15;
    const int qi = row & (T_ - 1);
    const int nc = (qi >> 7) / 8 + 1;
    const size_t pbase = (size_t)row * NCMAX;

    float mv[NCMAX];
#pragma unroll
    for (int cc = 0; cc < NCMAX; cc++) mv[cc] = (cc < nc) ? g_pm[pbase + cc] : -1e30f;
    float m = -1e30f;
#pragma unroll
    for (int cc = 0; cc < NCMAX; cc++) m = fmaxf(m, mv[cc]);

    float l = 0.f;
    float ox = 0.f, oy = 0.f, oz = 0.f, ow = 0.f;
#pragma unroll
    for (int cc = 0; cc < NCMAX; cc++) {
        if (cc < nc) {
            const float w = ex2f(mv[cc] - m);      // log2-domain partials
            l = fmaf(g_pl[pbase + cc], w, l);
            const float4 v = *reinterpret_cast<const float4*>(
                &g_po[(pbase + cc) * HS_ + part * 4]);
            ox = fmaf(w, v.x, ox); oy = fmaf(w, v.y, oy);
            oz = fmaf(w, v.z, oz); ow = fmaf(w, v.w, ow);
        }
    }
    const float inv = 1.0f / l;
    float4 r;
    r.x = ox * inv; r.y = oy * inv; r.z = oz * inv; r.w = ow * inv;
    *reinterpret_cast<float4*>(&out[(size_t)row * HS_ + part * 4]) = r;
}

// ---------------------------------------------------------------------------
extern "C" void kernel_launch(void* const* d_in, const int* in_sizes, int n_in,
                              void* d_out, int out_size)
{
    const float* x  = (const float*)d_in[0];
    const float* Wq = (const float*)d_in[1];
    const float* Wk = (const float*)d_in[2];
    const float* Wv = (const float*)d_in[3];
    float* out = (float*)d_out;

    cudaFuncSetAttribute(proj_kernel, cudaFuncAttributeMaxDynamicSharedMemorySize, PROJ_SMEM);
    cudaFuncSetAttribute(attn_kernel, cudaFuncAttributeMaxDynamicSharedMemorySize, SMEM_BYTES);

    wconv_kernel<<<6, 256>>>(Wq, Wk, Wv);
    proj_kernel<<<(B_ * T_) / 64, 256, PROJ_SMEM>>>(x);

    dim3 ag(80, B_);
    attn_kernel<<<ag, 256, SMEM_BYTES>>>();

    attn_reduce_kernel<<<(B_ * T_ * 16) / 256, 256>>>(out);
}